// round 1
// baseline (speedup 1.0000x reference)
#include <cuda_runtime.h>
#include <math.h>

#define B_   64
#define T_   1024
#define C_   192
#define BT_  (B_*T_)
#define NPROJ 29

// ---------------- scratch (device globals; no allocation) ----------------
__device__ float g_xT  [(size_t)BT_*C_];
__device__ float g_xc  [(size_t)BT_*C_];
__device__ float g_act [(size_t)BT_*C_];
__device__ float g_tmp [(size_t)BT_*C_];
__device__ float g_gout[(size_t)BT_*C_];
__device__ float g_cond[B_*C_];
__device__ float g_z0[BT_];
__device__ float g_z1[BT_];
__device__ float g_hp[(size_t)BT_*NPROJ];

__device__ __forceinline__ float gelu_exact(float x){
    return 0.5f*x*(1.0f + erff(x*0.70710678118654752f));
}

// ---------------- transpose x: (B,C,T) -> (B,T,C) ----------------
__global__ void k_transpose(const float* __restrict__ x, float* __restrict__ xT){
    __shared__ float tile[32][33];
    int b  = blockIdx.z;
    int c0 = blockIdx.y * 32;
    int t0 = blockIdx.x * 32;
    int tx = threadIdx.x, ty = threadIdx.y;     // 32 x 8
    const float* xb = x + (size_t)b*C_*T_;
#pragma unroll
    for (int i = 0; i < 4; i++){
        int c = c0 + ty + i*8;
        tile[ty + i*8][tx] = xb[(size_t)c*T_ + t0 + tx];
    }
    __syncthreads();
    float* ob = xT + (size_t)b*T_*C_;
#pragma unroll
    for (int i = 0; i < 4; i++){
        int t = t0 + ty + i*8;
        ob[(size_t)t*C_ + c0 + tx] = tile[tx][ty + i*8];
    }
}

// ---------------- cond[b,o] = sum_c embed[b,c]*cond_w[o,c] + cond_b[o] ----------------
__global__ void k_cond(const float* __restrict__ embed, const float* __restrict__ cw,
                       const float* __restrict__ cb, float* __restrict__ cond){
    int b = blockIdx.x, o = threadIdx.x;
    __shared__ float se[C_];
    se[o] = embed[b*C_ + o];
    __syncthreads();
    float s = cb[o];
    const float* wr = cw + (size_t)o*C_;
#pragma unroll 8
    for (int c = 0; c < C_; c++) s = fmaf(se[c], wr[c], s);
    cond[b*C_ + o] = s;
}

// ---------------- GEMM: Cout[row,o] = sum_c A[row,c]*W[o,c] + bias[o] (+cond[b,o]) (*mask[row]) ----------------
__global__ void __launch_bounds__(256) k_gemm192(
    const float* __restrict__ A, const float* __restrict__ W,
    const float* __restrict__ bias, const float* __restrict__ cond,
    const float* __restrict__ mask, float* __restrict__ Cout)
{
    __shared__ float As[32][64];
    __shared__ float Ws[32][64];
    const int row0 = blockIdx.x * 64;
    const int o0   = blockIdx.y * 64;
    const int tid  = threadIdx.x;
    const int lr = tid & 63;
    const int kq = tid >> 6;      // 0..3
    const int tx = tid & 15;
    const int ty = tid >> 4;
    float acc[4][4];
#pragma unroll
    for (int i = 0; i < 4; i++)
#pragma unroll
        for (int j = 0; j < 4; j++) acc[i][j] = 0.f;

    const float* Arow = A + (size_t)(row0 + lr)*C_;
    const float* Wrow = W + (size_t)(o0  + lr)*C_;
    for (int kc = 0; kc < C_; kc += 32){
        float4 a0 = *(const float4*)(Arow + kc + kq*4);
        float4 a1 = *(const float4*)(Arow + kc + kq*4 + 16);
        float4 w0 = *(const float4*)(Wrow + kc + kq*4);
        float4 w1 = *(const float4*)(Wrow + kc + kq*4 + 16);
        __syncthreads();
        As[kq*4+0][lr]=a0.x; As[kq*4+1][lr]=a0.y; As[kq*4+2][lr]=a0.z; As[kq*4+3][lr]=a0.w;
        As[kq*4+16][lr]=a1.x; As[kq*4+17][lr]=a1.y; As[kq*4+18][lr]=a1.z; As[kq*4+19][lr]=a1.w;
        Ws[kq*4+0][lr]=w0.x; Ws[kq*4+1][lr]=w0.y; Ws[kq*4+2][lr]=w0.z; Ws[kq*4+3][lr]=w0.w;
        Ws[kq*4+16][lr]=w1.x; Ws[kq*4+17][lr]=w1.y; Ws[kq*4+18][lr]=w1.z; Ws[kq*4+19][lr]=w1.w;
        __syncthreads();
#pragma unroll
        for (int k = 0; k < 32; k++){
            float4 av = *(const float4*)&As[k][ty*4];
            float4 wv = *(const float4*)&Ws[k][tx*4];
            acc[0][0]=fmaf(av.x,wv.x,acc[0][0]); acc[0][1]=fmaf(av.x,wv.y,acc[0][1]);
            acc[0][2]=fmaf(av.x,wv.z,acc[0][2]); acc[0][3]=fmaf(av.x,wv.w,acc[0][3]);
            acc[1][0]=fmaf(av.y,wv.x,acc[1][0]); acc[1][1]=fmaf(av.y,wv.y,acc[1][1]);
            acc[1][2]=fmaf(av.y,wv.z,acc[1][2]); acc[1][3]=fmaf(av.y,wv.w,acc[1][3]);
            acc[2][0]=fmaf(av.z,wv.x,acc[2][0]); acc[2][1]=fmaf(av.z,wv.y,acc[2][1]);
            acc[2][2]=fmaf(av.z,wv.z,acc[2][2]); acc[2][3]=fmaf(av.z,wv.w,acc[2][3]);
            acc[3][0]=fmaf(av.w,wv.x,acc[3][0]); acc[3][1]=fmaf(av.w,wv.y,acc[3][1]);
            acc[3][2]=fmaf(av.w,wv.z,acc[3][2]); acc[3][3]=fmaf(av.w,wv.w,acc[3][3]);
        }
    }
    const int ob = o0 + tx*4;
    float b0 = bias[ob+0], b1 = bias[ob+1], b2 = bias[ob+2], b3 = bias[ob+3];
#pragma unroll
    for (int i = 0; i < 4; i++){
        int row = row0 + ty*4 + i;
        int b = row >> 10;
        float m = mask ? mask[row] : 1.0f;
        float4 v;
        v.x = acc[i][0] + b0; v.y = acc[i][1] + b1;
        v.z = acc[i][2] + b2; v.w = acc[i][3] + b3;
        if (cond){
            const float* cp = cond + b*C_ + ob;
            v.x += cp[0]; v.y += cp[1]; v.z += cp[2]; v.w += cp[3];
        }
        v.x *= m; v.y *= m; v.z *= m; v.w *= m;
        *(float4*)(Cout + (size_t)row*C_ + ob) = v;
    }
}

// ---------------- depthwise conv3 (dilated) + LN(channel) + GELU ----------------
__global__ void __launch_bounds__(192) k_dw(
    const float* __restrict__ x, float* __restrict__ out,
    const float* __restrict__ dww, const float* __restrict__ dwb,
    const float* __restrict__ n1g, const float* __restrict__ n1b,
    const float* __restrict__ mask, int dil)
{
    int bt = blockIdx.x;
    int b = bt >> 10, t = bt & 1023;
    int c = threadIdx.x;
    const float* xb = x + (size_t)b*T_*C_;
    const float* mb = mask + b*T_;
    int tm = t - dil, tp = t + dil;
    float xl = 0.f, xr = 0.f;
    if (tm >= 0) xl = xb[(size_t)tm*C_ + c] * mb[tm];
    float xm = xb[(size_t)t*C_ + c] * mb[t];
    if (tp < T_) xr = xb[(size_t)tp*C_ + c] * mb[tp];
    float y = fmaf(dww[c*3+0], xl, fmaf(dww[c*3+1], xm, fmaf(dww[c*3+2], xr, dwb[c])));

    float s1 = y, s2 = y*y;
#pragma unroll
    for (int o = 16; o > 0; o >>= 1){
        s1 += __shfl_xor_sync(0xffffffffu, s1, o);
        s2 += __shfl_xor_sync(0xffffffffu, s2, o);
    }
    __shared__ float r1[6], r2[6];
    int w = c >> 5;
    if ((c & 31) == 0){ r1[w] = s1; r2[w] = s2; }
    __syncthreads();
    float tot = 0.f, tot2 = 0.f;
#pragma unroll
    for (int i = 0; i < 6; i++){ tot += r1[i]; tot2 += r2[i]; }
    float mean = tot * (1.f/192.f);
    float var  = tot2 * (1.f/192.f) - mean*mean;
    float yn = n1g[c]*(y - mean)*rsqrtf(var + 1e-5f) + n1b[c];
    out[(size_t)bt*C_ + c] = gelu_exact(yn);
}

// ---------------- LN(channel)+GELU+residual (+optional mask) ----------------
__global__ void __launch_bounds__(192) k_ln2(
    const float* __restrict__ gin, float* __restrict__ xio,
    const float* __restrict__ n2g, const float* __restrict__ n2b,
    const float* __restrict__ mask)
{
    int bt = blockIdx.x;
    int c = threadIdx.x;
    size_t idx = (size_t)bt*C_ + c;
    float y = gin[idx];
    float s1 = y, s2 = y*y;
#pragma unroll
    for (int o = 16; o > 0; o >>= 1){
        s1 += __shfl_xor_sync(0xffffffffu, s1, o);
        s2 += __shfl_xor_sync(0xffffffffu, s2, o);
    }
    __shared__ float r1[6], r2[6];
    int w = c >> 5;
    if ((c & 31) == 0){ r1[w] = s1; r2[w] = s2; }
    __syncthreads();
    float tot = 0.f, tot2 = 0.f;
#pragma unroll
    for (int i = 0; i < 6; i++){ tot += r1[i]; tot2 += r2[i]; }
    float mean = tot * (1.f/192.f);
    float var  = tot2 * (1.f/192.f) - mean*mean;
    float yn = n2g[c]*(y - mean)*rsqrtf(var + 1e-5f) + n2b[c];
    float v = xio[idx] + gelu_exact(yn);
    if (mask) v *= mask[bt];
    xio[idx] = v;
}

// ---------------- noise -> z0/z1 ----------------
__global__ void k_noise(const float* __restrict__ noise, float* __restrict__ z0, float* __restrict__ z1){
    int idx = blockIdx.x*256 + threadIdx.x;
    int b = idx >> 10, t = idx & 1023;
    z0[idx] = noise[(size_t)b*2*T_ + t];
    z1[idx] = noise[(size_t)b*2*T_ + T_ + t];
}

// ---------------- hh = pre_w[c]*x0[bt] + pre_b[c] + xc ----------------
__global__ void k_hh(const float* __restrict__ x0, const float* __restrict__ xc,
                     const float* __restrict__ prew, const float* __restrict__ preb,
                     float* __restrict__ act){
    size_t idx = (size_t)blockIdx.x*256 + threadIdx.x;
    int c = (int)(idx % C_);
    size_t bt = idx / C_;
    act[idx] = fmaf(prew[c], x0[bt], preb[c]) + xc[idx];
}

// ---------------- proj 29x192 GEMM ----------------
__global__ void __launch_bounds__(928) k_proj29(
    const float* __restrict__ hh, const float* __restrict__ w,
    const float* __restrict__ bias, const float* __restrict__ mask,
    float* __restrict__ out)
{
    __shared__ float sh[32][193];
    int tid = threadIdx.x;
    size_t base = (size_t)blockIdx.x * 32 * C_;
    for (int i = tid; i < 32*C_; i += 928)
        sh[i/C_][i%C_] = hh[base + i];
    __syncthreads();
    int tl = tid & 31, p = tid >> 5;
    if (p < NPROJ){
        float s = bias[p];
        const float* wp = w + (size_t)p*C_;
#pragma unroll 8
        for (int c = 0; c < C_; c++) s = fmaf(sh[tl][c], wp[c], s);
        int bt = blockIdx.x*32 + tl;
        out[(size_t)bt*NPROJ + p] = s * mask[bt];
    }
}

// ---------------- rational-quadratic spline inverse, per element ----------------
__global__ void k_rqs(const float* __restrict__ hp, float* __restrict__ z1,
                      float* __restrict__ z0, const float* __restrict__ mask)
{
    int bt = blockIdx.x*256 + threadIdx.x;
    const float* h = hp + (size_t)bt*NPROJ;
    const float sc = 0.07216878364870323f;   // 1/sqrt(192)

    float w[10], cw[11];
    {
        float u[10]; float mx = -1e30f;
#pragma unroll
        for (int j = 0; j < 10; j++){ u[j] = h[j]*sc; mx = fmaxf(mx, u[j]); }
        float s = 0.f;
#pragma unroll
        for (int j = 0; j < 10; j++){ u[j] = expf(u[j]-mx); s += u[j]; }
        float inv = 1.0f/s, accum = 0.f;
        cw[0] = -5.0f;
#pragma unroll
        for (int j = 0; j < 10; j++){
            float wj = 0.001f + 0.99f*u[j]*inv;
            accum += wj;
            cw[j+1] = 10.0f*accum - 5.0f;
        }
        cw[10] = 5.0f;
#pragma unroll
        for (int j = 0; j < 10; j++) w[j] = cw[j+1]-cw[j];
    }
    float hb[10], ch[11];
    {
        float u[10]; float mx = -1e30f;
#pragma unroll
        for (int j = 0; j < 10; j++){ u[j] = h[10+j]*sc; mx = fmaxf(mx, u[j]); }
        float s = 0.f;
#pragma unroll
        for (int j = 0; j < 10; j++){ u[j] = expf(u[j]-mx); s += u[j]; }
        float inv = 1.0f/s, accum = 0.f;
        ch[0] = -5.0f;
#pragma unroll
        for (int j = 0; j < 10; j++){
            float hj = 0.001f + 0.99f*u[j]*inv;
            accum += hj;
            ch[j+1] = 10.0f*accum - 5.0f;
        }
        ch[10] = 5.0f;
#pragma unroll
        for (int j = 0; j < 10; j++) hb[j] = ch[j+1]-ch[j];
    }
    float d[11];
    {
        const float ucst = 0.5413248546129181f;  // log(expm1(0.999))
        float v = (ucst > 20.f) ? ucst : log1pf(expf(ucst));
        d[0] = 0.001f + v; d[10] = d[0];
#pragma unroll
        for (int j = 1; j <= 9; j++){
            float u = h[19 + j];                 // ud[j-1] = h[20 + (j-1)]
            float spv = (u > 20.f) ? u : log1pf(expf(u));
            d[j] = 0.001f + spv;
        }
    }
    float xin = z1[bt];
    float xcl = fminf(fmaxf(xin, -5.f), 5.f);
    int idx = 0;
#pragma unroll
    for (int j = 0; j < 11; j++){
        float loc = ch[j] + ((j == 10) ? 1e-6f : 0.f);
        idx += (xcl >= loc) ? 1 : 0;
    }
    idx = min(max(idx - 1, 0), 9);
    float bw = w[idx], bcw = cw[idx], bh = hb[idx], bch = ch[idx];
    float d0 = d[idx], d1 = d[idx+1];
    float delta = bh / bw;
    float two = d0 + d1 - 2.f*delta;
    float y = xcl - bch;
    float a  = y*two + bh*(delta - d0);
    float bb = bh*d0 - y*two;
    float c  = -delta*y;
    float disc = fmaxf(bb*bb - 4.f*a*c, 0.f);
    float root = 2.f*c / (-bb - sqrtf(disc));
    float outv = root*bw + bcw;
    bool inside = (xin >= -5.f) && (xin <= 5.f);
    float res = inside ? outv : xin;
    float m = mask[bt];
    z1[bt] = res * m;
    z0[bt] = z0[bt] * m;
}

// ---------------- final affine ----------------
__global__ void k_final(const float* __restrict__ z, const float* __restrict__ ea_m,
                        const float* __restrict__ ea_logs, const float* __restrict__ mask,
                        float* __restrict__ out){
    int idx = blockIdx.x*256 + threadIdx.x;
    out[idx] = (z[idx] - ea_m[0]) * expf(-ea_logs[0]) * mask[idx];
}

// ================= host =================
extern "C" void kernel_launch(void* const* d_in, const int* in_sizes, int n_in,
                              void* d_out, int out_size)
{
    const float* x        = (const float*)d_in[0];
    const float* mask     = (const float*)d_in[1];
    const float* embed    = (const float*)d_in[2];
    const float* noise    = (const float*)d_in[3];
    const float* pre_w    = (const float*)d_in[4];
    const float* pre_b    = (const float*)d_in[5];
    const float* cond_w   = (const float*)d_in[6];
    const float* cond_b   = (const float*)d_in[7];
    const float* dds_dw_w = (const float*)d_in[8];
    const float* dds_dw_b = (const float*)d_in[9];
    const float* dds_pw_w = (const float*)d_in[10];
    const float* dds_pw_b = (const float*)d_in[11];
    const float* dds_n1_g = (const float*)d_in[12];
    const float* dds_n1_b = (const float*)d_in[13];
    const float* dds_n2_g = (const float*)d_in[14];
    const float* dds_n2_b = (const float*)d_in[15];
    const float* proj_w   = (const float*)d_in[16];
    const float* proj_b   = (const float*)d_in[17];
    const float* ea_m     = (const float*)d_in[18];
    const float* ea_logs  = (const float*)d_in[19];
    const float* cf_pre_w = (const float*)d_in[20];
    const float* cf_pre_b = (const float*)d_in[21];
    const float* cf_dw_w  = (const float*)d_in[22];
    const float* cf_dw_b  = (const float*)d_in[23];
    const float* cf_pw_w  = (const float*)d_in[24];
    const float* cf_pw_b  = (const float*)d_in[25];
    const float* cf_n1_g  = (const float*)d_in[26];
    const float* cf_n1_b  = (const float*)d_in[27];
    const float* cf_n2_g  = (const float*)d_in[28];
    const float* cf_n2_b  = (const float*)d_in[29];
    const float* cf_projw = (const float*)d_in[30];
    const float* cf_projb = (const float*)d_in[31];
    float* out = (float*)d_out;

    float *xT, *xc, *act, *tmp, *gout, *cond, *z0, *z1, *hp;
    cudaGetSymbolAddress((void**)&xT,   g_xT);
    cudaGetSymbolAddress((void**)&xc,   g_xc);
    cudaGetSymbolAddress((void**)&act,  g_act);
    cudaGetSymbolAddress((void**)&tmp,  g_tmp);
    cudaGetSymbolAddress((void**)&gout, g_gout);
    cudaGetSymbolAddress((void**)&cond, g_cond);
    cudaGetSymbolAddress((void**)&z0,   g_z0);
    cudaGetSymbolAddress((void**)&z1,   g_z1);
    cudaGetSymbolAddress((void**)&hp,   g_hp);

    const int dils[3] = {1, 3, 9};
    dim3 gg(BT_/64, C_/64);

    // transpose x -> (B,T,C)
    {
        dim3 tb(32, 8), tg(T_/32, C_/32, B_);
        k_transpose<<<tg, tb>>>(x, xT);
    }
    // cond vector
    k_cond<<<B_, C_>>>(embed, cond_w, cond_b, cond);
    // pre conv1x1 + cond add
    k_gemm192<<<gg, 256>>>(xT, pre_w, pre_b, cond, nullptr, act);
    // main DDS (3 layers)
    for (int l = 0; l < 3; l++){
        k_dw<<<BT_, 192>>>(act, tmp, dds_dw_w + (size_t)l*C_*3, dds_dw_b + (size_t)l*C_,
                           dds_n1_g + (size_t)l*C_, dds_n1_b + (size_t)l*C_, mask, dils[l]);
        k_gemm192<<<gg, 256>>>(tmp, dds_pw_w + (size_t)l*C_*C_, dds_pw_b + (size_t)l*C_,
                               nullptr, nullptr, gout);
        k_ln2<<<BT_, 192>>>(gout, act, dds_n2_g + (size_t)l*C_, dds_n2_b + (size_t)l*C_,
                            (l == 2) ? mask : nullptr);
    }
    // proj -> xc (g for flows)
    k_gemm192<<<gg, 256>>>(act, proj_w, proj_b, nullptr, mask, xc);

    // noise -> z
    k_noise<<<BT_/256, 256>>>(noise, z0, z1);

    float* cur0 = z0; float* cur1 = z1;
    const int forder[3] = {3, 2, 1};
    for (int fi = 0; fi < 3; fi++){
        int f = forder[fi];
        // flip channels
        float* tp_ = cur0; cur0 = cur1; cur1 = tp_;
        // hh = pre(x0) + xc
        k_hh<<<((size_t)BT_*C_)/256, 256>>>(cur0, xc, cf_pre_w + (size_t)f*C_, cf_pre_b + (size_t)f*C_, act);
        // DDS
        for (int l = 0; l < 3; l++){
            size_t o1 = ((size_t)f*3 + l)*C_;
            k_dw<<<BT_, 192>>>(act, tmp, cf_dw_w + o1*3, cf_dw_b + o1,
                               cf_n1_g + o1, cf_n1_b + o1, mask, dils[l]);
            k_gemm192<<<gg, 256>>>(tmp, cf_pw_w + o1*C_, cf_pw_b + o1, nullptr, nullptr, gout);
            k_ln2<<<BT_, 192>>>(gout, act, cf_n2_g + o1, cf_n2_b + o1,
                                (l == 2) ? mask : nullptr);
        }
        // proj 29 + spline inverse
        k_proj29<<<BT_/32, 928>>>(act, cf_projw + (size_t)f*NPROJ*C_, cf_projb + (size_t)f*NPROJ, mask, hp);
        k_rqs<<<BT_/256, 256>>>(hp, cur1, cur0, mask);
    }
    // final flip + affine
    { float* tp_ = cur0; cur0 = cur1; cur1 = tp_; }
    k_final<<<BT_/256, 256>>>(cur0, ea_m, ea_logs, mask, out);
}

// round 2
// speedup vs baseline: 1.5149x; 1.5149x over previous
#include <cuda_runtime.h>
#include <math.h>

#define B_   64
#define T_   1024
#define C_   192
#define BT_  (B_*T_)
#define NPROJ 29
#define ROWS 64
#define ASTR 68     // padded row stride for A tile (k-major): [192][68]
#define WSTR 196    // padded row stride for W chunk: [32][196]
#define SMEM_BYTES ((C_*ASTR + 32*WSTR) * 4)

// ---------------- scratch (device globals; no allocation) ----------------
__device__ float g_xT  [(size_t)BT_*C_];
__device__ float g_xc  [(size_t)BT_*C_];
__device__ float g_act [(size_t)BT_*C_];
__device__ float g_tmp [(size_t)BT_*C_];
__device__ float g_cond[B_*C_];
__device__ float g_z0[BT_];
__device__ float g_z1[BT_];
__device__ float g_hp[(size_t)BT_*NPROJ];

__device__ __forceinline__ float gelu_exact(float x){
    return 0.5f*x*(1.0f + erff(x*0.70710678118654752f));
}

// ---------------- transpose x: (B,C,T) -> (B,T,C) ----------------
__global__ void k_transpose(const float* __restrict__ x, float* __restrict__ xT){
    __shared__ float tile[32][33];
    int b  = blockIdx.z;
    int c0 = blockIdx.y * 32;
    int t0 = blockIdx.x * 32;
    int tx = threadIdx.x, ty = threadIdx.y;     // 32 x 8
    const float* xb = x + (size_t)b*C_*T_;
#pragma unroll
    for (int i = 0; i < 4; i++){
        int c = c0 + ty + i*8;
        tile[ty + i*8][tx] = xb[(size_t)c*T_ + t0 + tx];
    }
    __syncthreads();
    float* ob = xT + (size_t)b*T_*C_;
#pragma unroll
    for (int i = 0; i < 4; i++){
        int t = t0 + ty + i*8;
        ob[(size_t)t*C_ + c0 + tx] = tile[tx][ty + i*8];
    }
}

// ---------------- cond[b,o] ----------------
__global__ void k_cond(const float* __restrict__ embed, const float* __restrict__ cw,
                       const float* __restrict__ cb, float* __restrict__ cond){
    int b = blockIdx.x, o = threadIdx.x;
    __shared__ float se[C_];
    se[o] = embed[b*C_ + o];
    __syncthreads();
    float s = cb[o];
    const float* wr = cw + (size_t)o*C_;
#pragma unroll 8
    for (int c = 0; c < C_; c++) s = fmaf(se[c], wr[c], s);
    cond[b*C_ + o] = s;
}

// ============== shared GEMM core helpers (64 rows x 192 outs, 128 thr) ==============
// As: k-major [192][ASTR], Ws chunk [32][WSTR]; thread tile 8 rows x 12 cols.

__device__ __forceinline__ void gemm_core(const float* __restrict__ pww,
                                          float* As, float* Ws,
                                          float acc[8][12], int tx, int ty, int tid)
{
    for (int kc = 0; kc < C_; kc += 32){
        __syncthreads();   // protect Ws from previous iteration's readers
        {
            int q = tid & 7, colb = tid >> 3;   // 16 col bases
#pragma unroll
            for (int i2 = 0; i2 < 12; i2++){
                int col = colb + 16*i2;
                float4 v = *(const float4*)(pww + (size_t)col*C_ + kc + q*4);
                Ws[(q*4+0)*WSTR + col] = v.x;
                Ws[(q*4+1)*WSTR + col] = v.y;
                Ws[(q*4+2)*WSTR + col] = v.z;
                Ws[(q*4+3)*WSTR + col] = v.w;
            }
        }
        __syncthreads();
#pragma unroll 8
        for (int k = 0; k < 32; k++){
            float4 a0 = *(const float4*)&As[(kc+k)*ASTR + ty*8];
            float4 a1 = *(const float4*)&As[(kc+k)*ASTR + ty*8 + 4];
            float4 w0 = *(const float4*)&Ws[k*WSTR + tx*12];
            float4 w1 = *(const float4*)&Ws[k*WSTR + tx*12 + 4];
            float4 w2 = *(const float4*)&Ws[k*WSTR + tx*12 + 8];
            float av[8] = {a0.x,a0.y,a0.z,a0.w,a1.x,a1.y,a1.z,a1.w};
            float wv[12] = {w0.x,w0.y,w0.z,w0.w,w1.x,w1.y,w1.z,w1.w,w2.x,w2.y,w2.z,w2.w};
#pragma unroll
            for (int i = 0; i < 8; i++)
#pragma unroll
                for (int j = 0; j < 12; j++)
                    acc[i][j] = fmaf(av[i], wv[j], acc[i][j]);
        }
    }
}

// ---------------- fused DDS layer: dw+LN1+GELU -> GEMM -> LN2+GELU+res(+mask) ----------------
__global__ void __launch_bounds__(128) k_fused_layer(
    const float* __restrict__ xin, float* __restrict__ xout,
    const float* __restrict__ dww, const float* __restrict__ dwb,
    const float* __restrict__ n1g, const float* __restrict__ n1b,
    const float* __restrict__ pww, const float* __restrict__ pwb,
    const float* __restrict__ n2g, const float* __restrict__ n2b,
    const float* __restrict__ mask, int dil, int apply_mask)
{
    extern __shared__ float sm[];
    float* As = sm;
    float* Ws = sm + C_*ASTR;
    const int tid = threadIdx.x;
    const int bt0 = blockIdx.x * ROWS;
    const int b = bt0 >> 10;
    const int t0 = bt0 & 1023;
    const int lane = tid & 31, w = tid >> 5;
    const float* mb = mask + b*T_;
    const float* xb = xin + (size_t)b*T_*C_;

    // -------- prologue: depthwise conv3 + LN1 + GELU into As (k-major) --------
    for (int i = 0; i < 16; i++){
        int r = i*4 + w;
        int t = t0 + r;
        int tm = t - dil, tp = t + dil;
        float mm = mb[t];
        float ml = (tm >= 0)  ? mb[tm] : 0.f;
        float mr = (tp < T_)  ? mb[tp] : 0.f;
        const float* xm_ = xb + (size_t)t*C_;
        const float* xl_ = xb + (size_t)((tm >= 0) ? tm : 0)*C_;
        const float* xr_ = xb + (size_t)((tp < T_) ? tp : (T_-1))*C_;
        float y[6]; float s1 = 0.f, s2 = 0.f;
#pragma unroll
        for (int j = 0; j < 6; j++){
            int c = lane + 32*j;
            float vl = xl_[c]*ml, vm = xm_[c]*mm, vr = xr_[c]*mr;
            float v = fmaf(dww[c*3+0], vl, fmaf(dww[c*3+1], vm, fmaf(dww[c*3+2], vr, dwb[c])));
            y[j] = v; s1 += v; s2 += v*v;
        }
#pragma unroll
        for (int o = 16; o > 0; o >>= 1){
            s1 += __shfl_xor_sync(0xffffffffu, s1, o);
            s2 += __shfl_xor_sync(0xffffffffu, s2, o);
        }
        float mean = s1 * (1.f/192.f);
        float var  = s2 * (1.f/192.f) - mean*mean;
        float rstd = rsqrtf(var + 1e-5f);
#pragma unroll
        for (int j = 0; j < 6; j++){
            int c = lane + 32*j;
            float yn = n1g[c]*(y[j] - mean)*rstd + n1b[c];
            As[c*ASTR + r] = gelu_exact(yn);
        }
    }

    // -------- GEMM --------
    const int tx = tid & 15, ty = tid >> 4;
    float acc[8][12];
#pragma unroll
    for (int i = 0; i < 8; i++)
#pragma unroll
        for (int j = 0; j < 12; j++) acc[i][j] = 0.f;
    gemm_core(pww, As, Ws, acc, tx, ty, tid);

    // -------- epilogue: bias + LN2 + GELU + residual (+mask) --------
    float bb[12];
#pragma unroll
    for (int j = 0; j < 12; j++) bb[j] = pwb[tx*12 + j];
#pragma unroll
    for (int i = 0; i < 8; i++){
        int row = bt0 + ty*8 + i;
        float s1 = 0.f, s2 = 0.f;
#pragma unroll
        for (int j = 0; j < 12; j++){
            float v = acc[i][j] + bb[j];
            acc[i][j] = v; s1 += v; s2 += v*v;
        }
#pragma unroll
        for (int o = 8; o > 0; o >>= 1){
            s1 += __shfl_xor_sync(0xffffffffu, s1, o);
            s2 += __shfl_xor_sync(0xffffffffu, s2, o);
        }
        float mean = s1 * (1.f/192.f);
        float var  = s2 * (1.f/192.f) - mean*mean;
        float rstd = rsqrtf(var + 1e-5f);
        float m = apply_mask ? mask[row] : 1.f;
        size_t base = (size_t)row*C_ + tx*12;
#pragma unroll
        for (int j = 0; j < 12; j += 4){
            float4 res = *(const float4*)(xin + base + j);
            float4 o4;
            o4.x = res.x + gelu_exact(n2g[tx*12+j+0]*(acc[i][j+0]-mean)*rstd + n2b[tx*12+j+0]);
            o4.y = res.y + gelu_exact(n2g[tx*12+j+1]*(acc[i][j+1]-mean)*rstd + n2b[tx*12+j+1]);
            o4.z = res.z + gelu_exact(n2g[tx*12+j+2]*(acc[i][j+2]-mean)*rstd + n2b[tx*12+j+2]);
            o4.w = res.w + gelu_exact(n2g[tx*12+j+3]*(acc[i][j+3]-mean)*rstd + n2b[tx*12+j+3]);
            if (apply_mask){ o4.x *= m; o4.y *= m; o4.z *= m; o4.w *= m; }
            *(float4*)(xout + base + j) = o4;
        }
    }
}

// ---------------- plain GEMM (same tiling), optional cond add / mask ----------------
__global__ void __launch_bounds__(128) k_gemm_plain(
    const float* __restrict__ xin, float* __restrict__ xout,
    const float* __restrict__ pww, const float* __restrict__ pwb,
    const float* __restrict__ cond, const float* __restrict__ mask)
{
    extern __shared__ float sm[];
    float* As = sm;
    float* Ws = sm + C_*ASTR;
    const int tid = threadIdx.x;
    const int bt0 = blockIdx.x * ROWS;
    const int b = bt0 >> 10;
    const int lane = tid & 31, w = tid >> 5;

    for (int i = 0; i < 16; i++){
        int r = i*4 + w;
        const float* xr_ = xin + (size_t)(bt0 + r)*C_;
#pragma unroll
        for (int j = 0; j < 6; j++){
            int c = lane + 32*j;
            As[c*ASTR + r] = xr_[c];
        }
    }

    const int tx = tid & 15, ty = tid >> 4;
    float acc[8][12];
#pragma unroll
    for (int i = 0; i < 8; i++)
#pragma unroll
        for (int j = 0; j < 12; j++) acc[i][j] = 0.f;
    gemm_core(pww, As, Ws, acc, tx, ty, tid);

    float bb[12];
#pragma unroll
    for (int j = 0; j < 12; j++){
        bb[j] = pwb[tx*12 + j];
        if (cond) bb[j] += cond[b*C_ + tx*12 + j];
    }
#pragma unroll
    for (int i = 0; i < 8; i++){
        int row = bt0 + ty*8 + i;
        float m = mask ? mask[row] : 1.f;
        size_t base = (size_t)row*C_ + tx*12;
#pragma unroll
        for (int j = 0; j < 12; j += 4){
            float4 o4;
            o4.x = (acc[i][j+0] + bb[j+0]) * m;
            o4.y = (acc[i][j+1] + bb[j+1]) * m;
            o4.z = (acc[i][j+2] + bb[j+2]) * m;
            o4.w = (acc[i][j+3] + bb[j+3]) * m;
            *(float4*)(xout + base + j) = o4;
        }
    }
}

// ---------------- noise -> z0/z1 ----------------
__global__ void k_noise(const float* __restrict__ noise, float* __restrict__ z0, float* __restrict__ z1){
    int idx = blockIdx.x*256 + threadIdx.x;
    int b = idx >> 10, t = idx & 1023;
    z0[idx] = noise[(size_t)b*2*T_ + t];
    z1[idx] = noise[(size_t)b*2*T_ + T_ + t];
}

// ---------------- hh = pre_w[c]*x0[bt] + pre_b[c] + xc ----------------
__global__ void k_hh(const float* __restrict__ x0, const float* __restrict__ xc,
                     const float* __restrict__ prew, const float* __restrict__ preb,
                     float* __restrict__ act){
    size_t idx = (size_t)blockIdx.x*256 + threadIdx.x;
    int c = (int)(idx % C_);
    size_t bt = idx / C_;
    act[idx] = fmaf(prew[c], x0[bt], preb[c]) + xc[idx];
}

// ---------------- proj 29x192 GEMM ----------------
__global__ void __launch_bounds__(928) k_proj29(
    const float* __restrict__ hh, const float* __restrict__ w,
    const float* __restrict__ bias, const float* __restrict__ mask,
    float* __restrict__ out)
{
    __shared__ float sh[32][193];
    int tid = threadIdx.x;
    size_t base = (size_t)blockIdx.x * 32 * C_;
    for (int i = tid; i < 32*C_; i += 928)
        sh[i/C_][i%C_] = hh[base + i];
    __syncthreads();
    int tl = tid & 31, p = tid >> 5;
    if (p < NPROJ){
        float s = bias[p];
        const float* wp = w + (size_t)p*C_;
#pragma unroll 8
        for (int c = 0; c < C_; c++) s = fmaf(sh[tl][c], wp[c], s);
        int bt = blockIdx.x*32 + tl;
        out[(size_t)bt*NPROJ + p] = s * mask[bt];
    }
}

// ---------------- rational-quadratic spline inverse ----------------
__global__ void k_rqs(const float* __restrict__ hp, float* __restrict__ z1,
                      float* __restrict__ z0, const float* __restrict__ mask)
{
    int bt = blockIdx.x*256 + threadIdx.x;
    const float* h = hp + (size_t)bt*NPROJ;
    const float sc = 0.07216878364870323f;   // 1/sqrt(192)

    float w[10], cw[11];
    {
        float u[10]; float mx = -1e30f;
#pragma unroll
        for (int j = 0; j < 10; j++){ u[j] = h[j]*sc; mx = fmaxf(mx, u[j]); }
        float s = 0.f;
#pragma unroll
        for (int j = 0; j < 10; j++){ u[j] = expf(u[j]-mx); s += u[j]; }
        float inv = 1.0f/s, accum = 0.f;
        cw[0] = -5.0f;
#pragma unroll
        for (int j = 0; j < 10; j++){
            float wj = 0.001f + 0.99f*u[j]*inv;
            accum += wj;
            cw[j+1] = 10.0f*accum - 5.0f;
        }
        cw[10] = 5.0f;
#pragma unroll
        for (int j = 0; j < 10; j++) w[j] = cw[j+1]-cw[j];
    }
    float hb[10], ch[11];
    {
        float u[10]; float mx = -1e30f;
#pragma unroll
        for (int j = 0; j < 10; j++){ u[j] = h[10+j]*sc; mx = fmaxf(mx, u[j]); }
        float s = 0.f;
#pragma unroll
        for (int j = 0; j < 10; j++){ u[j] = expf(u[j]-mx); s += u[j]; }
        float inv = 1.0f/s, accum = 0.f;
        ch[0] = -5.0f;
#pragma unroll
        for (int j = 0; j < 10; j++){
            float hj = 0.001f + 0.99f*u[j]*inv;
            accum += hj;
            ch[j+1] = 10.0f*accum - 5.0f;
        }
        ch[10] = 5.0f;
#pragma unroll
        for (int j = 0; j < 10; j++) hb[j] = ch[j+1]-ch[j];
    }
    float d[11];
    {
        const float ucst = 0.5413248546129181f;  // log(expm1(0.999))
        float v = log1pf(expf(ucst));
        d[0] = 0.001f + v; d[10] = d[0];
#pragma unroll
        for (int j = 1; j <= 9; j++){
            float u = h[19 + j];
            float spv = (u > 20.f) ? u : log1pf(expf(u));
            d[j] = 0.001f + spv;
        }
    }
    float xin = z1[bt];
    float xcl = fminf(fmaxf(xin, -5.f), 5.f);
    int idx = 0;
#pragma unroll
    for (int j = 0; j < 11; j++){
        float loc = ch[j] + ((j == 10) ? 1e-6f : 0.f);
        idx += (xcl >= loc) ? 1 : 0;
    }
    idx = min(max(idx - 1, 0), 9);
    float bw = w[idx], bcw = cw[idx], bh = hb[idx], bch = ch[idx];
    float d0 = d[idx], d1 = d[idx+1];
    float delta = bh / bw;
    float two = d0 + d1 - 2.f*delta;
    float y = xcl - bch;
    float a  = y*two + bh*(delta - d0);
    float bbq = bh*d0 - y*two;
    float c  = -delta*y;
    float disc = fmaxf(bbq*bbq - 4.f*a*c, 0.f);
    float root = 2.f*c / (-bbq - sqrtf(disc));
    float outv = root*bw + bcw;
    bool inside = (xin >= -5.f) && (xin <= 5.f);
    float res = inside ? outv : xin;
    float m = mask[bt];
    z1[bt] = res * m;
    z0[bt] = z0[bt] * m;
}

// ---------------- final affine ----------------
__global__ void k_final(const float* __restrict__ z, const float* __restrict__ ea_m,
                        const float* __restrict__ ea_logs, const float* __restrict__ mask,
                        float* __restrict__ out){
    int idx = blockIdx.x*256 + threadIdx.x;
    out[idx] = (z[idx] - ea_m[0]) * expf(-ea_logs[0]) * mask[idx];
}

// ================= host =================
extern "C" void kernel_launch(void* const* d_in, const int* in_sizes, int n_in,
                              void* d_out, int out_size)
{
    const float* x        = (const float*)d_in[0];
    const float* mask     = (const float*)d_in[1];
    const float* embed    = (const float*)d_in[2];
    const float* noise    = (const float*)d_in[3];
    const float* pre_w    = (const float*)d_in[4];
    const float* pre_b    = (const float*)d_in[5];
    const float* cond_w   = (const float*)d_in[6];
    const float* cond_b   = (const float*)d_in[7];
    const float* dds_dw_w = (const float*)d_in[8];
    const float* dds_dw_b = (const float*)d_in[9];
    const float* dds_pw_w = (const float*)d_in[10];
    const float* dds_pw_b = (const float*)d_in[11];
    const float* dds_n1_g = (const float*)d_in[12];
    const float* dds_n1_b = (const float*)d_in[13];
    const float* dds_n2_g = (const float*)d_in[14];
    const float* dds_n2_b = (const float*)d_in[15];
    const float* proj_w   = (const float*)d_in[16];
    const float* proj_b   = (const float*)d_in[17];
    const float* ea_m     = (const float*)d_in[18];
    const float* ea_logs  = (const float*)d_in[19];
    const float* cf_pre_w = (const float*)d_in[20];
    const float* cf_pre_b = (const float*)d_in[21];
    const float* cf_dw_w  = (const float*)d_in[22];
    const float* cf_dw_b  = (const float*)d_in[23];
    const float* cf_pw_w  = (const float*)d_in[24];
    const float* cf_pw_b  = (const float*)d_in[25];
    const float* cf_n1_g  = (const float*)d_in[26];
    const float* cf_n1_b  = (const float*)d_in[27];
    const float* cf_n2_g  = (const float*)d_in[28];
    const float* cf_n2_b  = (const float*)d_in[29];
    const float* cf_projw = (const float*)d_in[30];
    const float* cf_projb = (const float*)d_in[31];
    float* out = (float*)d_out;

    float *xT, *xc, *act, *tmp, *cond, *z0, *z1, *hp;
    cudaGetSymbolAddress((void**)&xT,   g_xT);
    cudaGetSymbolAddress((void**)&xc,   g_xc);
    cudaGetSymbolAddress((void**)&act,  g_act);
    cudaGetSymbolAddress((void**)&tmp,  g_tmp);
    cudaGetSymbolAddress((void**)&cond, g_cond);
    cudaGetSymbolAddress((void**)&z0,   g_z0);
    cudaGetSymbolAddress((void**)&z1,   g_z1);
    cudaGetSymbolAddress((void**)&hp,   g_hp);

    static int smem_set = 0;
    if (!smem_set){
        cudaFuncSetAttribute(k_fused_layer, cudaFuncAttributeMaxDynamicSharedMemorySize, SMEM_BYTES);
        cudaFuncSetAttribute(k_gemm_plain,  cudaFuncAttributeMaxDynamicSharedMemorySize, SMEM_BYTES);
        smem_set = 1;
    }

    const int dils[3] = {1, 3, 9};
    const int NB = BT_/ROWS;   // 1024 blocks

    // transpose x -> (B,T,C)
    {
        dim3 tb(32, 8), tg(T_/32, C_/32, B_);
        k_transpose<<<tg, tb>>>(x, xT);
    }
    k_cond<<<B_, C_>>>(embed, cond_w, cond_b, cond);
    // pre conv1x1 + cond add -> act
    k_gemm_plain<<<NB, 128, SMEM_BYTES>>>(xT, act, pre_w, pre_b, cond, nullptr);
    // main DDS (3 layers), ping-pong act <-> tmp; result in tmp
    {
        float* bin = act; float* bout = tmp;
        for (int l = 0; l < 3; l++){
            k_fused_layer<<<NB, 128, SMEM_BYTES>>>(bin, bout,
                dds_dw_w + (size_t)l*C_*3, dds_dw_b + (size_t)l*C_,
                dds_n1_g + (size_t)l*C_, dds_n1_b + (size_t)l*C_,
                dds_pw_w + (size_t)l*C_*C_, dds_pw_b + (size_t)l*C_,
                dds_n2_g + (size_t)l*C_, dds_n2_b + (size_t)l*C_,
                mask, dils[l], (l == 2) ? 1 : 0);
            float* t_ = bin; bin = bout; bout = t_;
        }
        // result in bin (== tmp after 3 swaps)
        k_gemm_plain<<<NB, 128, SMEM_BYTES>>>(bin, xc, proj_w, proj_b, nullptr, mask);
    }

    // noise -> z
    k_noise<<<BT_/256, 256>>>(noise, z0, z1);

    float* cur0 = z0; float* cur1 = z1;
    const int forder[3] = {3, 2, 1};
    for (int fi = 0; fi < 3; fi++){
        int f = forder[fi];
        // flip channels
        float* tp_ = cur0; cur0 = cur1; cur1 = tp_;
        // hh = pre(x0) + xc -> act
        k_hh<<<((size_t)BT_*C_)/256, 256>>>(cur0, xc, cf_pre_w + (size_t)f*C_, cf_pre_b + (size_t)f*C_, act);
        // DDS
        float* bin = act; float* bout = tmp;
        for (int l = 0; l < 3; l++){
            size_t o1 = ((size_t)f*3 + l)*C_;
            k_fused_layer<<<NB, 128, SMEM_BYTES>>>(bin, bout,
                cf_dw_w + o1*3, cf_dw_b + o1,
                cf_n1_g + o1, cf_n1_b + o1,
                cf_pw_w + o1*C_, cf_pw_b + o1,
                cf_n2_g + o1, cf_n2_b + o1,
                mask, dils[l], (l == 2) ? 1 : 0);
            float* t_ = bin; bin = bout; bout = t_;
        }
        // proj 29 + spline inverse (DDS result is in bin == tmp)
        k_proj29<<<BT_/32, 928>>>(bin, cf_projw + (size_t)f*NPROJ*C_, cf_projb + (size_t)f*NPROJ, mask, hp);
        k_rqs<<<BT_/256, 256>>>(hp, cur1, cur0, mask);
    }
    // final flip + affine
    { float* tp_ = cur0; cur0 = cur1; cur1 = tp_; }
    k_final<<<BT_/256, 256>>>(cur0, ea_m, ea_logs, mask, out);
}

// round 5
// speedup vs baseline: 2.3409x; 1.5452x over previous
#include <cuda_runtime.h>
#include <math.h>
#include <stdint.h>

#define B_   64
#define T_   1024
#define C_   192
#define BT_  (B_*T_)
#define NPROJ 29

#define ASTRIDE 196
#define WSTRIDE 196
#define A_ELEMS (64*ASTRIDE)
#define W_ELEMS (192*WSTRIDE)
#define RED_OFF (A_ELEMS + W_ELEMS)
#define SMEM_MMA ((RED_OFF + 512) * 4)   // 202752 bytes

// ---------------- scratch ----------------
__device__ float g_xT  [(size_t)BT_*C_];
__device__ float g_xc  [(size_t)BT_*C_];
__device__ float g_act [(size_t)BT_*C_];
__device__ float g_tmp [(size_t)BT_*C_];
__device__ float g_cond[B_*C_];
__device__ float g_z0[BT_];
__device__ float g_z1[BT_];
__device__ float g_hp[(size_t)BT_*NPROJ];

__device__ __forceinline__ float gelu_exact(float x){
    return 0.5f*x*(1.0f + erff(x*0.70710678118654752f));
}
__device__ __forceinline__ uint32_t to_tf32(float f){
    uint32_t r; asm("cvt.rna.tf32.f32 %0, %1;" : "=r"(r) : "f"(f)); return r;
}
__device__ __forceinline__ void mma1688(float* d, const uint32_t* a, const uint32_t* b){
    asm volatile("mma.sync.aligned.m16n8k8.row.col.f32.tf32.tf32.f32 "
                 "{%0,%1,%2,%3}, {%4,%5,%6,%7}, {%8,%9}, {%0,%1,%2,%3};"
                 : "+f"(d[0]), "+f"(d[1]), "+f"(d[2]), "+f"(d[3])
                 : "r"(a[0]), "r"(a[1]), "r"(a[2]), "r"(a[3]),
                   "r"(b[0]), "r"(b[1]));
}

// warp-tiled tf32 GEMM core: A smem [64][ASTRIDE] (row r, k), W smem [192][WSTRIDE] (col n, k)
// 8 warps: wm = wid>>2 (M32 each), wn = wid&3 (N48 each). acc[t(2)][n(6)][4].
__device__ __forceinline__ void mma_core(const uint32_t* Asm, const uint32_t* Wsm,
                                         float acc[2][6][4], int wm, int wn, int lane)
{
    const int r = lane >> 2, q = lane & 3;
    const uint32_t* ab = Asm + (wm*32 + r)*ASTRIDE + q;
    const uint32_t* wb = Wsm + (wn*48 + r)*WSTRIDE + q;
#pragma unroll 4
    for (int kc = 0; kc < C_; kc += 8){
        uint32_t a[2][4];
#pragma unroll
        for (int t = 0; t < 2; t++){
            const uint32_t* p = ab + t*16*ASTRIDE + kc;
            a[t][0] = p[0];
            a[t][1] = p[8*ASTRIDE];
            a[t][2] = p[4];
            a[t][3] = p[8*ASTRIDE + 4];
        }
        uint32_t b[6][2];
#pragma unroll
        for (int n = 0; n < 6; n++){
            const uint32_t* p = wb + n*8*WSTRIDE + kc;
            b[n][0] = p[0];
            b[n][1] = p[4];
        }
#pragma unroll
        for (int t = 0; t < 2; t++)
#pragma unroll
            for (int n = 0; n < 6; n++)
                mma1688(acc[t][n], a[t], b[n]);
    }
}

__device__ __forceinline__ void stage_W(const float* __restrict__ pww, uint32_t* Wsm, int tid){
#pragma unroll
    for (int j = 0; j < 36; j++){
        int i = tid + j*256;
        int n = i / 48, kq = i % 48;
        float4 v = *(const float4*)(pww + (size_t)n*C_ + kq*4);
        uint32_t* p = Wsm + n*WSTRIDE + kq*4;
        p[0] = to_tf32(v.x); p[1] = to_tf32(v.y); p[2] = to_tf32(v.z); p[3] = to_tf32(v.w);
    }
}

// ---------------- fused DDS layer: dw+LN1+GELU -> tf32 MMA -> LN2+GELU+res(+mask) ----------------
__global__ void __launch_bounds__(256,1) k_layer_mma(
    const float* __restrict__ xin, float* __restrict__ xout,
    const float* __restrict__ dww, const float* __restrict__ dwb,
    const float* __restrict__ n1g, const float* __restrict__ n1b,
    const float* __restrict__ pww, const float* __restrict__ pwb,
    const float* __restrict__ n2g, const float* __restrict__ n2b,
    const float* __restrict__ mask, int dil, int apply_mask)
{
    extern __shared__ uint32_t sm[];
    uint32_t* Asm = sm;
    uint32_t* Wsm = sm + A_ELEMS;
    float* red1 = (float*)(sm + RED_OFF);       // [4][64]
    float* red2 = red1 + 256;
    const int tid = threadIdx.x;
    const int w = tid >> 5, lane = tid & 31;
    const int bt0 = blockIdx.x * 64;
    const int b = bt0 >> 10, t0 = bt0 & 1023;

    stage_W(pww, Wsm, tid);

    // prologue: dwconv + LN1 + GELU -> A smem (tf32)
    {
        const float* mb = mask + b*T_;
        const float* xb = xin + (size_t)b*T_*C_;
#pragma unroll 1
        for (int i = 0; i < 8; i++){
            int r = i*8 + w;                 // 0..63
            int t = t0 + r;
            int tm = t - dil, tp = t + dil;
            float mm = mb[t];
            float ml = (tm >= 0) ? mb[tm] : 0.f;
            float mr = (tp < T_) ? mb[tp] : 0.f;
            const float* xm_ = xb + (size_t)t*C_;
            const float* xl_ = xb + (size_t)((tm >= 0) ? tm : 0)*C_;
            const float* xr_ = xb + (size_t)((tp < T_) ? tp : (T_-1))*C_;
            float y[6]; float s1 = 0.f, s2 = 0.f;
#pragma unroll
            for (int j = 0; j < 6; j++){
                int c = lane + 32*j;
                float v = fmaf(dww[c*3+0], xl_[c]*ml,
                          fmaf(dww[c*3+1], xm_[c]*mm,
                          fmaf(dww[c*3+2], xr_[c]*mr, dwb[c])));
                y[j] = v; s1 += v; s2 += v*v;
            }
#pragma unroll
            for (int o = 16; o > 0; o >>= 1){
                s1 += __shfl_xor_sync(0xffffffffu, s1, o);
                s2 += __shfl_xor_sync(0xffffffffu, s2, o);
            }
            float mean = s1*(1.f/192.f);
            float var  = s2*(1.f/192.f) - mean*mean;
            float rstd = rsqrtf(var + 1e-5f);
#pragma unroll
            for (int j = 0; j < 6; j++){
                int c = lane + 32*j;
                float yn = n1g[c]*(y[j] - mean)*rstd + n1b[c];
                Asm[r*ASTRIDE + c] = to_tf32(gelu_exact(yn));
            }
        }
    }
    __syncthreads();

    const int wm = w >> 2, wn = w & 3;
    float acc[2][6][4];
#pragma unroll
    for (int t = 0; t < 2; t++)
#pragma unroll
        for (int n = 0; n < 6; n++)
#pragma unroll
            for (int k = 0; k < 4; k++) acc[t][n][k] = 0.f;
    mma_core(Asm, Wsm, acc, wm, wn, lane);

    // ---------------- epilogue ----------------
    const int r = lane >> 2, q = lane & 3;
    float bias0[6], bias1[6];
#pragma unroll
    for (int n = 0; n < 6; n++){
        int col = wn*48 + n*8 + q*2;
        bias0[n] = pwb[col]; bias1[n] = pwb[col+1];
    }
    // per-thread row partial sums: rows (wm*32 + t*16 + r) and (+8)
    float s1[2][2] = {{0,0},{0,0}}, s2[2][2] = {{0,0},{0,0}};
#pragma unroll
    for (int t = 0; t < 2; t++)
#pragma unroll
        for (int n = 0; n < 6; n++){
            float v0 = acc[t][n][0] + bias0[n];
            float v1 = acc[t][n][1] + bias1[n];
            float v2 = acc[t][n][2] + bias0[n];
            float v3 = acc[t][n][3] + bias1[n];
            s1[t][0] += v0 + v1; s2[t][0] += v0*v0 + v1*v1;
            s1[t][1] += v2 + v3; s2[t][1] += v2*v2 + v3*v3;
        }
#pragma unroll
    for (int t = 0; t < 2; t++)
#pragma unroll
        for (int h = 0; h < 2; h++){
#pragma unroll
            for (int o = 1; o < 4; o <<= 1){
                s1[t][h] += __shfl_xor_sync(0xffffffffu, s1[t][h], o);
                s2[t][h] += __shfl_xor_sync(0xffffffffu, s2[t][h], o);
            }
        }
    if (q == 0){
#pragma unroll
        for (int t = 0; t < 2; t++)
#pragma unroll
            for (int h = 0; h < 2; h++){
                int row = wm*32 + t*16 + h*8 + r;
                red1[wn*64 + row] = s1[t][h];
                red2[wn*64 + row] = s2[t][h];
            }
    }
    __syncthreads();

#pragma unroll
    for (int t = 0; t < 2; t++)
#pragma unroll
        for (int h = 0; h < 2; h++){
            int row = wm*32 + t*16 + h*8 + r;
            float tot1 = red1[row] + red1[64+row] + red1[128+row] + red1[192+row];
            float tot2 = red2[row] + red2[64+row] + red2[128+row] + red2[192+row];
            float mean = tot1*(1.f/192.f);
            float var  = tot2*(1.f/192.f) - mean*mean;
            float rstd = rsqrtf(var + 1e-5f);
            int grow = bt0 + row;
            float m = apply_mask ? mask[grow] : 1.f;
            const float* resp = xin + (size_t)grow*C_;
            float* outp = xout + (size_t)grow*C_;
#pragma unroll
            for (int n = 0; n < 6; n++){
                int col = wn*48 + n*8 + q*2;
                float v0 = acc[t][n][h*2+0] + bias0[n];
                float v1 = acc[t][n][h*2+1] + bias1[n];
                float2 res = *(const float2*)(resp + col);
                float2 o2;
                o2.x = res.x + gelu_exact(n2g[col+0]*(v0-mean)*rstd + n2b[col+0]);
                o2.y = res.y + gelu_exact(n2g[col+1]*(v1-mean)*rstd + n2b[col+1]);
                if (apply_mask){ o2.x *= m; o2.y *= m; }
                *(float2*)(outp + col) = o2;
            }
        }
}

// ---------------- plain tf32 MMA GEMM: out = xin @ W^T + b (+cond[b]) (*mask) ----------------
__global__ void __launch_bounds__(256,1) k_gemm_mma(
    const float* __restrict__ xin, float* __restrict__ xout,
    const float* __restrict__ pww, const float* __restrict__ pwb,
    const float* __restrict__ cond, const float* __restrict__ mask)
{
    extern __shared__ uint32_t sm[];
    uint32_t* Asm = sm;
    uint32_t* Wsm = sm + A_ELEMS;
    const int tid = threadIdx.x;
    const int w = tid >> 5, lane = tid & 31;
    const int bt0 = blockIdx.x * 64;
    const int b = bt0 >> 10;

    stage_W(pww, Wsm, tid);
    // A copy (64 x 192)
#pragma unroll
    for (int j = 0; j < 12; j++){
        int i = tid + j*256;
        int r2 = i / 48, kq = i % 48;
        float4 v = *(const float4*)(xin + (size_t)(bt0 + r2)*C_ + kq*4);
        uint32_t* p = Asm + r2*ASTRIDE + kq*4;
        p[0] = to_tf32(v.x); p[1] = to_tf32(v.y); p[2] = to_tf32(v.z); p[3] = to_tf32(v.w);
    }
    __syncthreads();

    const int wm = w >> 2, wn = w & 3;
    float acc[2][6][4];
#pragma unroll
    for (int t = 0; t < 2; t++)
#pragma unroll
        for (int n = 0; n < 6; n++)
#pragma unroll
            for (int k = 0; k < 4; k++) acc[t][n][k] = 0.f;
    mma_core(Asm, Wsm, acc, wm, wn, lane);

    const int r = lane >> 2, q = lane & 3;
    float bias0[6], bias1[6];
#pragma unroll
    for (int n = 0; n < 6; n++){
        int col = wn*48 + n*8 + q*2;
        bias0[n] = pwb[col]; bias1[n] = pwb[col+1];
        if (cond){ bias0[n] += cond[b*C_ + col]; bias1[n] += cond[b*C_ + col+1]; }
    }
#pragma unroll
    for (int t = 0; t < 2; t++)
#pragma unroll
        for (int h = 0; h < 2; h++){
            int row = wm*32 + t*16 + h*8 + r;
            int grow = bt0 + row;
            float m = mask ? mask[grow] : 1.f;
            float* outp = xout + (size_t)grow*C_;
#pragma unroll
            for (int n = 0; n < 6; n++){
                int col = wn*48 + n*8 + q*2;
                float2 o2;
                o2.x = (acc[t][n][h*2+0] + bias0[n]) * m;
                o2.y = (acc[t][n][h*2+1] + bias1[n]) * m;
                *(float2*)(outp + col) = o2;
            }
        }
}

// ---------------- transpose x: (B,C,T) -> (B,T,C) ----------------
__global__ void k_transpose(const float* __restrict__ x, float* __restrict__ xT){
    __shared__ float tile[32][33];
    int b  = blockIdx.z;
    int c0 = blockIdx.y * 32;
    int t0 = blockIdx.x * 32;
    int tx = threadIdx.x, ty = threadIdx.y;
    const float* xb = x + (size_t)b*C_*T_;
#pragma unroll
    for (int i = 0; i < 4; i++){
        int c = c0 + ty + i*8;
        tile[ty + i*8][tx] = xb[(size_t)c*T_ + t0 + tx];
    }
    __syncthreads();
    float* ob = xT + (size_t)b*T_*C_;
#pragma unroll
    for (int i = 0; i < 4; i++){
        int t = t0 + ty + i*8;
        ob[(size_t)t*C_ + c0 + tx] = tile[tx][ty + i*8];
    }
}

// ---------------- cond[b,o] ----------------
__global__ void k_cond(const float* __restrict__ embed, const float* __restrict__ cw,
                       const float* __restrict__ cb, float* __restrict__ cond){
    int b = blockIdx.x, o = threadIdx.x;
    __shared__ float se[C_];
    se[o] = embed[b*C_ + o];
    __syncthreads();
    float s = cb[o];
    const float* wr = cw + (size_t)o*C_;
#pragma unroll 8
    for (int c = 0; c < C_; c++) s = fmaf(se[c], wr[c], s);
    cond[b*C_ + o] = s;
}

// ---------------- noise -> z0/z1 ----------------
__global__ void k_noise(const float* __restrict__ noise, float* __restrict__ z0, float* __restrict__ z1){
    int idx = blockIdx.x*256 + threadIdx.x;
    int b = idx >> 10, t = idx & 1023;
    z0[idx] = noise[(size_t)b*2*T_ + t];
    z1[idx] = noise[(size_t)b*2*T_ + T_ + t];
}

// ---------------- hh = pre_w[c]*x0[bt] + pre_b[c] + xc ----------------
__global__ void k_hh(const float* __restrict__ x0, const float* __restrict__ xc,
                     const float* __restrict__ prew, const float* __restrict__ preb,
                     float* __restrict__ act){
    size_t idx = (size_t)blockIdx.x*256 + threadIdx.x;
    int c = (int)(idx % C_);
    size_t bt = idx / C_;
    act[idx] = fmaf(prew[c], x0[bt], preb[c]) + xc[idx];
}

// ---------------- proj 29x192 GEMM ----------------
__global__ void __launch_bounds__(928) k_proj29(
    const float* __restrict__ hh, const float* __restrict__ w,
    const float* __restrict__ bias, const float* __restrict__ mask,
    float* __restrict__ out)
{
    __shared__ float sh[32][193];
    int tid = threadIdx.x;
    size_t base = (size_t)blockIdx.x * 32 * C_;
    for (int i = tid; i < 32*C_; i += 928)
        sh[i/C_][i%C_] = hh[base + i];
    __syncthreads();
    int tl = tid & 31, p = tid >> 5;
    if (p < NPROJ){
        float s = bias[p];
        const float* wp = w + (size_t)p*C_;
#pragma unroll 8
        for (int c = 0; c < C_; c++) s = fmaf(sh[tl][c], wp[c], s);
        int bt = blockIdx.x*32 + tl;
        out[(size_t)bt*NPROJ + p] = s * mask[bt];
    }
}

// ---------------- rational-quadratic spline inverse ----------------
__global__ void k_rqs(const float* __restrict__ hp, float* __restrict__ z1,
                      float* __restrict__ z0, const float* __restrict__ mask)
{
    int bt = blockIdx.x*256 + threadIdx.x;
    const float* h = hp + (size_t)bt*NPROJ;
    const float sc = 0.07216878364870323f;

    float w[10], cw[11];
    {
        float u[10]; float mx = -1e30f;
#pragma unroll
        for (int j = 0; j < 10; j++){ u[j] = h[j]*sc; mx = fmaxf(mx, u[j]); }
        float s = 0.f;
#pragma unroll
        for (int j = 0; j < 10; j++){ u[j] = expf(u[j]-mx); s += u[j]; }
        float inv = 1.0f/s, accum = 0.f;
        cw[0] = -5.0f;
#pragma unroll
        for (int j = 0; j < 10; j++){
            float wj = 0.001f + 0.99f*u[j]*inv;
            accum += wj;
            cw[j+1] = 10.0f*accum - 5.0f;
        }
        cw[10] = 5.0f;
#pragma unroll
        for (int j = 0; j < 10; j++) w[j] = cw[j+1]-cw[j];
    }
    float hb[10], ch[11];
    {
        float u[10]; float mx = -1e30f;
#pragma unroll
        for (int j = 0; j < 10; j++){ u[j] = h[10+j]*sc; mx = fmaxf(mx, u[j]); }
        float s = 0.f;
#pragma unroll
        for (int j = 0; j < 10; j++){ u[j] = expf(u[j]-mx); s += u[j]; }
        float inv = 1.0f/s, accum = 0.f;
        ch[0] = -5.0f;
#pragma unroll
        for (int j = 0; j < 10; j++){
            float hj = 0.001f + 0.99f*u[j]*inv;
            accum += hj;
            ch[j+1] = 10.0f*accum - 5.0f;
        }
        ch[10] = 5.0f;
#pragma unroll
        for (int j = 0; j < 10; j++) hb[j] = ch[j+1]-ch[j];
    }
    float d[11];
    {
        const float ucst = 0.5413248546129181f;
        float v = log1pf(expf(ucst));
        d[0] = 0.001f + v; d[10] = d[0];
#pragma unroll
        for (int j = 1; j <= 9; j++){
            float u = h[19 + j];
            float spv = (u > 20.f) ? u : log1pf(expf(u));
            d[j] = 0.001f + spv;
        }
    }
    float xin = z1[bt];
    float xcl = fminf(fmaxf(xin, -5.f), 5.f);
    int idx = 0;
#pragma unroll
    for (int j = 0; j < 11; j++){
        float loc = ch[j] + ((j == 10) ? 1e-6f : 0.f);
        idx += (xcl >= loc) ? 1 : 0;
    }
    idx = min(max(idx - 1, 0), 9);
    float bw = w[idx], bcw = cw[idx], bh = hb[idx], bch = ch[idx];
    float d0 = d[idx], d1 = d[idx+1];
    float delta = bh / bw;
    float two = d0 + d1 - 2.f*delta;
    float y = xcl - bch;
    float a  = y*two + bh*(delta - d0);
    float bbq = bh*d0 - y*two;
    float c  = -delta*y;
    float disc = fmaxf(bbq*bbq - 4.f*a*c, 0.f);
    float root = 2.f*c / (-bbq - sqrtf(disc));
    float outv = root*bw + bcw;
    bool inside = (xin >= -5.f) && (xin <= 5.f);
    float res = inside ? outv : xin;
    float m = mask[bt];
    z1[bt] = res * m;
    z0[bt] = z0[bt] * m;
}

// ---------------- final affine ----------------
__global__ void k_final(const float* __restrict__ z, const float* __restrict__ ea_m,
                        const float* __restrict__ ea_logs, const float* __restrict__ mask,
                        float* __restrict__ out){
    int idx = blockIdx.x*256 + threadIdx.x;
    out[idx] = (z[idx] - ea_m[0]) * expf(-ea_logs[0]) * mask[idx];
}

// ================= host =================
extern "C" void kernel_launch(void* const* d_in, const int* in_sizes, int n_in,
                              void* d_out, int out_size)
{
    const float* x        = (const float*)d_in[0];
    const float* mask     = (const float*)d_in[1];
    const float* embed    = (const float*)d_in[2];
    const float* noise    = (const float*)d_in[3];
    const float* pre_w    = (const float*)d_in[4];
    const float* pre_b    = (const float*)d_in[5];
    const float* cond_w   = (const float*)d_in[6];
    const float* cond_b   = (const float*)d_in[7];
    const float* dds_dw_w = (const float*)d_in[8];
    const float* dds_dw_b = (const float*)d_in[9];
    const float* dds_pw_w = (const float*)d_in[10];
    const float* dds_pw_b = (const float*)d_in[11];
    const float* dds_n1_g = (const float*)d_in[12];
    const float* dds_n1_b = (const float*)d_in[13];
    const float* dds_n2_g = (const float*)d_in[14];
    const float* dds_n2_b = (const float*)d_in[15];
    const float* proj_w   = (const float*)d_in[16];
    const float* proj_b   = (const float*)d_in[17];
    const float* ea_m     = (const float*)d_in[18];
    const float* ea_logs  = (const float*)d_in[19];
    const float* cf_pre_w = (const float*)d_in[20];
    const float* cf_pre_b = (const float*)d_in[21];
    const float* cf_dw_w  = (const float*)d_in[22];
    const float* cf_dw_b  = (const float*)d_in[23];
    const float* cf_pw_w  = (const float*)d_in[24];
    const float* cf_pw_b  = (const float*)d_in[25];
    const float* cf_n1_g  = (const float*)d_in[26];
    const float* cf_n1_b  = (const float*)d_in[27];
    const float* cf_n2_g  = (const float*)d_in[28];
    const float* cf_n2_b  = (const float*)d_in[29];
    const float* cf_projw = (const float*)d_in[30];
    const float* cf_projb = (const float*)d_in[31];
    float* out = (float*)d_out;

    float *xT, *xc, *act, *tmp, *cond, *z0, *z1, *hp;
    cudaGetSymbolAddress((void**)&xT,   g_xT);
    cudaGetSymbolAddress((void**)&xc,   g_xc);
    cudaGetSymbolAddress((void**)&act,  g_act);
    cudaGetSymbolAddress((void**)&tmp,  g_tmp);
    cudaGetSymbolAddress((void**)&cond, g_cond);
    cudaGetSymbolAddress((void**)&z0,   g_z0);
    cudaGetSymbolAddress((void**)&z1,   g_z1);
    cudaGetSymbolAddress((void**)&hp,   g_hp);

    cudaFuncSetAttribute(k_layer_mma, cudaFuncAttributeMaxDynamicSharedMemorySize, SMEM_MMA);
    cudaFuncSetAttribute(k_gemm_mma,  cudaFuncAttributeMaxDynamicSharedMemorySize, SMEM_MMA);

    const int dils[3] = {1, 3, 9};
    const int NB = BT_/64;   // 1024 blocks

    {
        dim3 tb(32, 8), tg(T_/32, C_/32, B_);
        k_transpose<<<tg, tb>>>(x, xT);
    }
    k_cond<<<B_, C_>>>(embed, cond_w, cond_b, cond);
    k_gemm_mma<<<NB, 256, SMEM_MMA>>>(xT, act, pre_w, pre_b, cond, nullptr);
    {
        float* bin = act; float* bout = tmp;
        for (int l = 0; l < 3; l++){
            k_layer_mma<<<NB, 256, SMEM_MMA>>>(bin, bout,
                dds_dw_w + (size_t)l*C_*3, dds_dw_b + (size_t)l*C_,
                dds_n1_g + (size_t)l*C_, dds_n1_b + (size_t)l*C_,
                dds_pw_w + (size_t)l*C_*C_, dds_pw_b + (size_t)l*C_,
                dds_n2_g + (size_t)l*C_, dds_n2_b + (size_t)l*C_,
                mask, dils[l], (l == 2) ? 1 : 0);
            float* t_ = bin; bin = bout; bout = t_;
        }
        k_gemm_mma<<<NB, 256, SMEM_MMA>>>(bin, xc, proj_w, proj_b, nullptr, mask);
    }

    k_noise<<<BT_/256, 256>>>(noise, z0, z1);

    float* cur0 = z0; float* cur1 = z1;
    const int forder[3] = {3, 2, 1};
    for (int fi = 0; fi < 3; fi++){
        int f = forder[fi];
        float* tp_ = cur0; cur0 = cur1; cur1 = tp_;
        k_hh<<<((size_t)BT_*C_)/256, 256>>>(cur0, xc, cf_pre_w + (size_t)f*C_, cf_pre_b + (size_t)f*C_, act);
        float* bin = act; float* bout = tmp;
        for (int l = 0; l < 3; l++){
            size_t o1 = ((size_t)f*3 + l)*C_;
            k_layer_mma<<<NB, 256, SMEM_MMA>>>(bin, bout,
                cf_dw_w + o1*3, cf_dw_b + o1,
                cf_n1_g + o1, cf_n1_b + o1,
                cf_pw_w + o1*C_, cf_pw_b + o1,
                cf_n2_g + o1, cf_n2_b + o1,
                mask, dils[l], (l == 2) ? 1 : 0);
            float* t_ = bin; bin = bout; bout = t_;
        }
        k_proj29<<<BT_/32, 928>>>(bin, cf_projw + (size_t)f*NPROJ*C_, cf_projb + (size_t)f*NPROJ, mask, hp);
        k_rqs<<<BT_/256, 256>>>(hp, cur1, cur0, mask);
    }
    { float* tp_ = cur0; cur0 = cur1; cur1 = tp_; }
    k_final<<<BT_/256, 256>>>(cur0, ea_m, ea_logs, mask, out);
}

// round 6
// speedup vs baseline: 2.4149x; 1.0316x over previous
#include <cuda_runtime.h>
#include <math.h>
#include <stdint.h>

#define B_   64
#define T_   1024
#define C_   192
#define BT_  (B_*T_)
#define NPROJ 29

#define ASTRIDE 196
#define WSTRIDE 196
#define A_ELEMS (64*ASTRIDE)
#define W_ELEMS (192*WSTRIDE)
#define RED_OFF (A_ELEMS + W_ELEMS)
#define SMEM_MMA ((RED_OFF + 1024) * 4)

// ---------------- scratch ----------------
__device__ float g_xT  [(size_t)BT_*C_];
__device__ float g_xc  [(size_t)BT_*C_];
__device__ float g_act [(size_t)BT_*C_];
__device__ float g_tmp [(size_t)BT_*C_];
__device__ float g_cond[B_*C_];
__device__ float g_z0[BT_];
__device__ float g_z1[BT_];
__device__ float g_hp[(size_t)BT_*NPROJ];

__device__ __forceinline__ float gelu_exact(float x){
    return 0.5f*x*(1.0f + erff(x*0.70710678118654752f));
}
__device__ __forceinline__ uint32_t to_tf32(float f){
    uint32_t r; asm("cvt.rna.tf32.f32 %0, %1;" : "=r"(r) : "f"(f)); return r;
}
__device__ __forceinline__ void mma1688(float* d, const uint32_t* a, const uint32_t* b){
    asm volatile("mma.sync.aligned.m16n8k8.row.col.f32.tf32.tf32.f32 "
                 "{%0,%1,%2,%3}, {%4,%5,%6,%7}, {%8,%9}, {%0,%1,%2,%3};"
                 : "+f"(d[0]), "+f"(d[1]), "+f"(d[2]), "+f"(d[3])
                 : "r"(a[0]), "r"(a[1]), "r"(a[2]), "r"(a[3]),
                   "r"(b[0]), "r"(b[1]));
}

// 16 warps: wm = w>>3 (M32 each), wn = w&7 (N24 each). acc[t(2)][n(3)][4].
__device__ __forceinline__ void mma_core(const uint32_t* Asm, const uint32_t* Wsm,
                                         float acc[2][3][4], int wm, int wn, int lane)
{
    const int r = lane >> 2, q = lane & 3;
    const uint32_t* ab = Asm + (wm*32 + r)*ASTRIDE + q;
    const uint32_t* wb = Wsm + (wn*24 + r)*WSTRIDE + q;
#pragma unroll 4
    for (int kc = 0; kc < C_; kc += 8){
        uint32_t a[2][4];
#pragma unroll
        for (int t = 0; t < 2; t++){
            const uint32_t* p = ab + t*16*ASTRIDE + kc;
            a[t][0] = p[0];
            a[t][1] = p[8*ASTRIDE];
            a[t][2] = p[4];
            a[t][3] = p[8*ASTRIDE + 4];
        }
        uint32_t b[3][2];
#pragma unroll
        for (int n = 0; n < 3; n++){
            const uint32_t* p = wb + n*8*WSTRIDE + kc;
            b[n][0] = p[0];
            b[n][1] = p[4];
        }
#pragma unroll
        for (int t = 0; t < 2; t++)
#pragma unroll
            for (int n = 0; n < 3; n++)
                mma1688(acc[t][n], a[t], b[n]);
    }
}

__device__ __forceinline__ void stage_W(const float* __restrict__ pww, uint32_t* Wsm, int tid){
#pragma unroll
    for (int j = 0; j < 18; j++){
        int i = tid + j*512;
        int n = i / 48, kq = i % 48;
        float4 v = *(const float4*)(pww + (size_t)n*C_ + kq*4);
        uint32_t* p = Wsm + n*WSTRIDE + kq*4;
        p[0] = to_tf32(v.x); p[1] = to_tf32(v.y); p[2] = to_tf32(v.z); p[3] = to_tf32(v.w);
    }
}

// ---------------- fused DDS layer (2 chunks of 64 rows per block) ----------------
// hh_mode: input rows are hh = prew[c]*x0[bt] + preb[c] + xin[bt,c]  (xin := xc)
__global__ void __launch_bounds__(512,1) k_layer_mma(
    const float* __restrict__ xin, float* __restrict__ xout,
    const float* __restrict__ dww, const float* __restrict__ dwb,
    const float* __restrict__ n1g, const float* __restrict__ n1b,
    const float* __restrict__ pww, const float* __restrict__ pwb,
    const float* __restrict__ n2g, const float* __restrict__ n2b,
    const float* __restrict__ mask, int dil, int apply_mask,
    const float* __restrict__ x0g, const float* __restrict__ prew,
    const float* __restrict__ preb, int hh_mode)
{
    extern __shared__ uint32_t sm[];
    uint32_t* Asm = sm;
    uint32_t* Wsm = sm + A_ELEMS;
    float* red1 = (float*)(sm + RED_OFF);       // [8][64]
    float* red2 = red1 + 512;
    const int tid = threadIdx.x;
    const int w = tid >> 5, lane = tid & 31;
    const int bt0 = blockIdx.x * 128;
    const int b = bt0 >> 10, t0 = bt0 & 1023;
    const float* mb = mask + b*T_;
    const float* xb = xin + (size_t)b*T_*C_;
    const float* x0b = hh_mode ? (x0g + b*T_) : (const float*)0;

    stage_W(pww, Wsm, tid);

    const int wm = w >> 3, wn = w & 7;
    const int r = lane >> 2, q = lane & 3;

    for (int ch = 0; ch < 2; ch++){
        __syncthreads();   // Wsm staged (ch0) / red+Asm free (ch1)
        const int t0c = t0 + ch*64;

        // ---- prologue: dwconv + LN1 + GELU -> Asm ----
#pragma unroll 1
        for (int i = 0; i < 4; i++){
            int rr = i*16 + w;               // 0..63
            int t = t0c + rr;
            int tm = t - dil, tp = t + dil;
            float mm = mb[t];
            float ml = (tm >= 0) ? mb[tm] : 0.f;
            float mr = (tp < T_) ? mb[tp] : 0.f;
            int tmc = (tm >= 0) ? tm : 0;
            int tpc = (tp < T_) ? tp : (T_-1);
            const float* xm_ = xb + (size_t)t*C_;
            const float* xl_ = xb + (size_t)tmc*C_;
            const float* xr_ = xb + (size_t)tpc*C_;
            float x0m = 0.f, x0l = 0.f, x0r = 0.f;
            if (hh_mode){ x0m = x0b[t]; x0l = x0b[tmc]; x0r = x0b[tpc]; }
            float y[6]; float s1 = 0.f, s2 = 0.f;
#pragma unroll
            for (int j = 0; j < 6; j++){
                int c = lane + 32*j;
                float vl = xl_[c], vm = xm_[c], vr = xr_[c];
                if (hh_mode){
                    float pw = prew[c], pb = preb[c];
                    vl = fmaf(pw, x0l, pb) + vl;
                    vm = fmaf(pw, x0m, pb) + vm;
                    vr = fmaf(pw, x0r, pb) + vr;
                }
                float v = fmaf(dww[c*3+0], vl*ml,
                          fmaf(dww[c*3+1], vm*mm,
                          fmaf(dww[c*3+2], vr*mr, dwb[c])));
                y[j] = v; s1 += v; s2 += v*v;
            }
#pragma unroll
            for (int o = 16; o > 0; o >>= 1){
                s1 += __shfl_xor_sync(0xffffffffu, s1, o);
                s2 += __shfl_xor_sync(0xffffffffu, s2, o);
            }
            float mean = s1*(1.f/192.f);
            float var  = s2*(1.f/192.f) - mean*mean;
            float rstd = rsqrtf(var + 1e-5f);
#pragma unroll
            for (int j = 0; j < 6; j++){
                int c = lane + 32*j;
                float yn = n1g[c]*(y[j] - mean)*rstd + n1b[c];
                Asm[rr*ASTRIDE + c] = to_tf32(gelu_exact(yn));
            }
        }
        __syncthreads();

        // ---- MMA ----
        float acc[2][3][4];
#pragma unroll
        for (int t = 0; t < 2; t++)
#pragma unroll
            for (int n = 0; n < 3; n++)
#pragma unroll
                for (int k = 0; k < 4; k++) acc[t][n][k] = 0.f;
        mma_core(Asm, Wsm, acc, wm, wn, lane);

        // ---- epilogue ----
        float bias0[3], bias1[3];
#pragma unroll
        for (int n = 0; n < 3; n++){
            int col = wn*24 + n*8 + q*2;
            bias0[n] = pwb[col]; bias1[n] = pwb[col+1];
        }
        float s1a[2][2] = {{0,0},{0,0}}, s2a[2][2] = {{0,0},{0,0}};
#pragma unroll
        for (int t = 0; t < 2; t++)
#pragma unroll
            for (int n = 0; n < 3; n++){
                float v0 = acc[t][n][0] + bias0[n];
                float v1 = acc[t][n][1] + bias1[n];
                float v2 = acc[t][n][2] + bias0[n];
                float v3 = acc[t][n][3] + bias1[n];
                s1a[t][0] += v0 + v1; s2a[t][0] += v0*v0 + v1*v1;
                s1a[t][1] += v2 + v3; s2a[t][1] += v2*v2 + v3*v3;
            }
#pragma unroll
        for (int t = 0; t < 2; t++)
#pragma unroll
            for (int h = 0; h < 2; h++){
#pragma unroll
                for (int o = 1; o < 4; o <<= 1){
                    s1a[t][h] += __shfl_xor_sync(0xffffffffu, s1a[t][h], o);
                    s2a[t][h] += __shfl_xor_sync(0xffffffffu, s2a[t][h], o);
                }
            }
        if (q == 0){
#pragma unroll
            for (int t = 0; t < 2; t++)
#pragma unroll
                for (int h = 0; h < 2; h++){
                    int row = wm*32 + t*16 + h*8 + r;
                    red1[wn*64 + row] = s1a[t][h];
                    red2[wn*64 + row] = s2a[t][h];
                }
        }
        __syncthreads();

#pragma unroll
        for (int t = 0; t < 2; t++)
#pragma unroll
            for (int h = 0; h < 2; h++){
                int row = wm*32 + t*16 + h*8 + r;
                float tot1 = 0.f, tot2 = 0.f;
#pragma unroll
                for (int k = 0; k < 8; k++){ tot1 += red1[k*64+row]; tot2 += red2[k*64+row]; }
                float mean = tot1*(1.f/192.f);
                float var  = tot2*(1.f/192.f) - mean*mean;
                float rstd = rsqrtf(var + 1e-5f);
                int grow = bt0 + ch*64 + row;
                float m = apply_mask ? mask[grow] : 1.f;
                float x0v = hh_mode ? x0g[grow] : 0.f;
                const float* resp = xin + (size_t)grow*C_;
                float* outp = xout + (size_t)grow*C_;
#pragma unroll
                for (int n = 0; n < 3; n++){
                    int col = wn*24 + n*8 + q*2;
                    float v0 = acc[t][n][h*2+0] + bias0[n];
                    float v1 = acc[t][n][h*2+1] + bias1[n];
                    float2 res = *(const float2*)(resp + col);
                    float rx = res.x, ry = res.y;
                    if (hh_mode){
                        rx = fmaf(prew[col+0], x0v, preb[col+0]) + rx;
                        ry = fmaf(prew[col+1], x0v, preb[col+1]) + ry;
                    }
                    float2 o2;
                    o2.x = rx + gelu_exact(n2g[col+0]*(v0-mean)*rstd + n2b[col+0]);
                    o2.y = ry + gelu_exact(n2g[col+1]*(v1-mean)*rstd + n2b[col+1]);
                    if (apply_mask){ o2.x *= m; o2.y *= m; }
                    *(float2*)(outp + col) = o2;
                }
            }
    }
}

// ---------------- plain tf32 MMA GEMM (2 chunks of 64 rows per block) ----------------
__global__ void __launch_bounds__(512,1) k_gemm_mma(
    const float* __restrict__ xin, float* __restrict__ xout,
    const float* __restrict__ pww, const float* __restrict__ pwb,
    const float* __restrict__ cond, const float* __restrict__ mask)
{
    extern __shared__ uint32_t sm[];
    uint32_t* Asm = sm;
    uint32_t* Wsm = sm + A_ELEMS;
    const int tid = threadIdx.x;
    const int w = tid >> 5, lane = tid & 31;
    const int bt0 = blockIdx.x * 128;
    const int b = bt0 >> 10;

    stage_W(pww, Wsm, tid);

    const int wm = w >> 3, wn = w & 7;
    const int r = lane >> 2, q = lane & 3;

    for (int ch = 0; ch < 2; ch++){
        __syncthreads();
        const int rb = bt0 + ch*64;
#pragma unroll
        for (int j = 0; j < 6; j++){
            int i = tid + j*512;
            int r2 = i / 48, kq = i % 48;
            float4 v = *(const float4*)(xin + (size_t)(rb + r2)*C_ + kq*4);
            uint32_t* p = Asm + r2*ASTRIDE + kq*4;
            p[0] = to_tf32(v.x); p[1] = to_tf32(v.y); p[2] = to_tf32(v.z); p[3] = to_tf32(v.w);
        }
        __syncthreads();

        float acc[2][3][4];
#pragma unroll
        for (int t = 0; t < 2; t++)
#pragma unroll
            for (int n = 0; n < 3; n++)
#pragma unroll
                for (int k = 0; k < 4; k++) acc[t][n][k] = 0.f;
        mma_core(Asm, Wsm, acc, wm, wn, lane);

        float bias0[3], bias1[3];
#pragma unroll
        for (int n = 0; n < 3; n++){
            int col = wn*24 + n*8 + q*2;
            bias0[n] = pwb[col]; bias1[n] = pwb[col+1];
            if (cond){ bias0[n] += cond[b*C_ + col]; bias1[n] += cond[b*C_ + col+1]; }
        }
#pragma unroll
        for (int t = 0; t < 2; t++)
#pragma unroll
            for (int h = 0; h < 2; h++){
                int row = wm*32 + t*16 + h*8 + r;
                int grow = rb + row;
                float m = mask ? mask[grow] : 1.f;
                float* outp = xout + (size_t)grow*C_;
#pragma unroll
                for (int n = 0; n < 3; n++){
                    int col = wn*24 + n*8 + q*2;
                    float2 o2;
                    o2.x = (acc[t][n][h*2+0] + bias0[n]) * m;
                    o2.y = (acc[t][n][h*2+1] + bias1[n]) * m;
                    *(float2*)(outp + col) = o2;
                }
            }
    }
}

// ---------------- transpose x: (B,C,T) -> (B,T,C) ----------------
__global__ void k_transpose(const float* __restrict__ x, float* __restrict__ xT){
    __shared__ float tile[32][33];
    int b  = blockIdx.z;
    int c0 = blockIdx.y * 32;
    int t0 = blockIdx.x * 32;
    int tx = threadIdx.x, ty = threadIdx.y;
    const float* xb = x + (size_t)b*C_*T_;
#pragma unroll
    for (int i = 0; i < 4; i++){
        int c = c0 + ty + i*8;
        tile[ty + i*8][tx] = xb[(size_t)c*T_ + t0 + tx];
    }
    __syncthreads();
    float* ob = xT + (size_t)b*T_*C_;
#pragma unroll
    for (int i = 0; i < 4; i++){
        int t = t0 + ty + i*8;
        ob[(size_t)t*C_ + c0 + tx] = tile[tx][ty + i*8];
    }
}

// ---------------- cond[b,o] ----------------
__global__ void k_cond(const float* __restrict__ embed, const float* __restrict__ cw,
                       const float* __restrict__ cb, float* __restrict__ cond){
    int b = blockIdx.x, o = threadIdx.x;
    __shared__ float se[C_];
    se[o] = embed[b*C_ + o];
    __syncthreads();
    float s = cb[o];
    const float* wr = cw + (size_t)o*C_;
#pragma unroll 8
    for (int c = 0; c < C_; c++) s = fmaf(se[c], wr[c], s);
    cond[b*C_ + o] = s;
}

// ---------------- noise -> z0/z1 ----------------
__global__ void k_noise(const float* __restrict__ noise, float* __restrict__ z0, float* __restrict__ z1){
    int idx = blockIdx.x*256 + threadIdx.x;
    int b = idx >> 10, t = idx & 1023;
    z0[idx] = noise[(size_t)b*2*T_ + t];
    z1[idx] = noise[(size_t)b*2*T_ + T_ + t];
}

// ---------------- proj 29x192 GEMM ----------------
__global__ void __launch_bounds__(928) k_proj29(
    const float* __restrict__ hh, const float* __restrict__ w,
    const float* __restrict__ bias, const float* __restrict__ mask,
    float* __restrict__ out)
{
    __shared__ float sh[32][193];
    int tid = threadIdx.x;
    size_t base = (size_t)blockIdx.x * 32 * C_;
    for (int i = tid; i < 32*C_; i += 928)
        sh[i/C_][i%C_] = hh[base + i];
    __syncthreads();
    int tl = tid & 31, p = tid >> 5;
    if (p < NPROJ){
        float s = bias[p];
        const float* wp = w + (size_t)p*C_;
#pragma unroll 8
        for (int c = 0; c < C_; c++) s = fmaf(sh[tl][c], wp[c], s);
        int bt = blockIdx.x*32 + tl;
        out[(size_t)bt*NPROJ + p] = s * mask[bt];
    }
}

// ---------------- rational-quadratic spline inverse ----------------
__global__ void k_rqs(const float* __restrict__ hp, float* __restrict__ z1,
                      float* __restrict__ z0, const float* __restrict__ mask)
{
    int bt = blockIdx.x*256 + threadIdx.x;
    const float* h = hp + (size_t)bt*NPROJ;
    const float sc = 0.07216878364870323f;

    float w[10], cw[11];
    {
        float u[10]; float mx = -1e30f;
#pragma unroll
        for (int j = 0; j < 10; j++){ u[j] = h[j]*sc; mx = fmaxf(mx, u[j]); }
        float s = 0.f;
#pragma unroll
        for (int j = 0; j < 10; j++){ u[j] = expf(u[j]-mx); s += u[j]; }
        float inv = 1.0f/s, accum = 0.f;
        cw[0] = -5.0f;
#pragma unroll
        for (int j = 0; j < 10; j++){
            float wj = 0.001f + 0.99f*u[j]*inv;
            accum += wj;
            cw[j+1] = 10.0f*accum - 5.0f;
        }
        cw[10] = 5.0f;
#pragma unroll
        for (int j = 0; j < 10; j++) w[j] = cw[j+1]-cw[j];
    }
    float hb[10], ch[11];
    {
        float u[10]; float mx = -1e30f;
#pragma unroll
        for (int j = 0; j < 10; j++){ u[j] = h[10+j]*sc; mx = fmaxf(mx, u[j]); }
        float s = 0.f;
#pragma unroll
        for (int j = 0; j < 10; j++){ u[j] = expf(u[j]-mx); s += u[j]; }
        float inv = 1.0f/s, accum = 0.f;
        ch[0] = -5.0f;
#pragma unroll
        for (int j = 0; j < 10; j++){
            float hj = 0.001f + 0.99f*u[j]*inv;
            accum += hj;
            ch[j+1] = 10.0f*accum - 5.0f;
        }
        ch[10] = 5.0f;
#pragma unroll
        for (int j = 0; j < 10; j++) hb[j] = ch[j+1]-ch[j];
    }
    float d[11];
    {
        const float ucst = 0.5413248546129181f;
        float v = log1pf(expf(ucst));
        d[0] = 0.001f + v; d[10] = d[0];
#pragma unroll
        for (int j = 1; j <= 9; j++){
            float u = h[19 + j];
            float spv = (u > 20.f) ? u : log1pf(expf(u));
            d[j] = 0.001f + spv;
        }
    }
    float xin = z1[bt];
    float xcl = fminf(fmaxf(xin, -5.f), 5.f);
    int idx = 0;
#pragma unroll
    for (int j = 0; j < 11; j++){
        float loc = ch[j] + ((j == 10) ? 1e-6f : 0.f);
        idx += (xcl >= loc) ? 1 : 0;
    }
    idx = min(max(idx - 1, 0), 9);
    float bw = w[idx], bcw = cw[idx], bh = hb[idx], bch = ch[idx];
    float d0 = d[idx], d1 = d[idx+1];
    float delta = bh / bw;
    float two = d0 + d1 - 2.f*delta;
    float y = xcl - bch;
    float a  = y*two + bh*(delta - d0);
    float bbq = bh*d0 - y*two;
    float c  = -delta*y;
    float disc = fmaxf(bbq*bbq - 4.f*a*c, 0.f);
    float root = 2.f*c / (-bbq - sqrtf(disc));
    float outv = root*bw + bcw;
    bool inside = (xin >= -5.f) && (xin <= 5.f);
    float res = inside ? outv : xin;
    float m = mask[bt];
    z1[bt] = res * m;
    z0[bt] = z0[bt] * m;
}

// ---------------- final affine ----------------
__global__ void k_final(const float* __restrict__ z, const float* __restrict__ ea_m,
                        const float* __restrict__ ea_logs, const float* __restrict__ mask,
                        float* __restrict__ out){
    int idx = blockIdx.x*256 + threadIdx.x;
    out[idx] = (z[idx] - ea_m[0]) * expf(-ea_logs[0]) * mask[idx];
}

// ================= host =================
extern "C" void kernel_launch(void* const* d_in, const int* in_sizes, int n_in,
                              void* d_out, int out_size)
{
    const float* x        = (const float*)d_in[0];
    const float* mask     = (const float*)d_in[1];
    const float* embed    = (const float*)d_in[2];
    const float* noise    = (const float*)d_in[3];
    const float* pre_w    = (const float*)d_in[4];
    const float* pre_b    = (const float*)d_in[5];
    const float* cond_w   = (const float*)d_in[6];
    const float* cond_b   = (const float*)d_in[7];
    const float* dds_dw_w = (const float*)d_in[8];
    const float* dds_dw_b = (const float*)d_in[9];
    const float* dds_pw_w = (const float*)d_in[10];
    const float* dds_pw_b = (const float*)d_in[11];
    const float* dds_n1_g = (const float*)d_in[12];
    const float* dds_n1_b = (const float*)d_in[13];
    const float* dds_n2_g = (const float*)d_in[14];
    const float* dds_n2_b = (const float*)d_in[15];
    const float* proj_w   = (const float*)d_in[16];
    const float* proj_b   = (const float*)d_in[17];
    const float* ea_m     = (const float*)d_in[18];
    const float* ea_logs  = (const float*)d_in[19];
    const float* cf_pre_w = (const float*)d_in[20];
    const float* cf_pre_b = (const float*)d_in[21];
    const float* cf_dw_w  = (const float*)d_in[22];
    const float* cf_dw_b  = (const float*)d_in[23];
    const float* cf_pw_w  = (const float*)d_in[24];
    const float* cf_pw_b  = (const float*)d_in[25];
    const float* cf_n1_g  = (const float*)d_in[26];
    const float* cf_n1_b  = (const float*)d_in[27];
    const float* cf_n2_g  = (const float*)d_in[28];
    const float* cf_n2_b  = (const float*)d_in[29];
    const float* cf_projw = (const float*)d_in[30];
    const float* cf_projb = (const float*)d_in[31];
    float* out = (float*)d_out;

    float *xT, *xc, *act, *tmp, *cond, *z0, *z1, *hp;
    cudaGetSymbolAddress((void**)&xT,   g_xT);
    cudaGetSymbolAddress((void**)&xc,   g_xc);
    cudaGetSymbolAddress((void**)&act,  g_act);
    cudaGetSymbolAddress((void**)&tmp,  g_tmp);
    cudaGetSymbolAddress((void**)&cond, g_cond);
    cudaGetSymbolAddress((void**)&z0,   g_z0);
    cudaGetSymbolAddress((void**)&z1,   g_z1);
    cudaGetSymbolAddress((void**)&hp,   g_hp);

    cudaFuncSetAttribute(k_layer_mma, cudaFuncAttributeMaxDynamicSharedMemorySize, SMEM_MMA);
    cudaFuncSetAttribute(k_gemm_mma,  cudaFuncAttributeMaxDynamicSharedMemorySize, SMEM_MMA);

    const int dils[3] = {1, 3, 9};
    const int NB = BT_/128;   // 512 blocks

    {
        dim3 tb(32, 8), tg(T_/32, C_/32, B_);
        k_transpose<<<tg, tb>>>(x, xT);
    }
    k_cond<<<B_, C_>>>(embed, cond_w, cond_b, cond);
    k_gemm_mma<<<NB, 512, SMEM_MMA>>>(xT, act, pre_w, pre_b, cond, nullptr);
    {
        float* bin = act; float* bout = tmp;
        for (int l = 0; l < 3; l++){
            k_layer_mma<<<NB, 512, SMEM_MMA>>>(bin, bout,
                dds_dw_w + (size_t)l*C_*3, dds_dw_b + (size_t)l*C_,
                dds_n1_g + (size_t)l*C_, dds_n1_b + (size_t)l*C_,
                dds_pw_w + (size_t)l*C_*C_, dds_pw_b + (size_t)l*C_,
                dds_n2_g + (size_t)l*C_, dds_n2_b + (size_t)l*C_,
                mask, dils[l], (l == 2) ? 1 : 0,
                nullptr, nullptr, nullptr, 0);
            float* t_ = bin; bin = bout; bout = t_;
        }
        k_gemm_mma<<<NB, 512, SMEM_MMA>>>(bin, xc, proj_w, proj_b, nullptr, mask);
    }

    k_noise<<<BT_/256, 256>>>(noise, z0, z1);

    float* cur0 = z0; float* cur1 = z1;
    const int forder[3] = {3, 2, 1};
    for (int fi = 0; fi < 3; fi++){
        int f = forder[fi];
        float* tp_ = cur0; cur0 = cur1; cur1 = tp_;
        // layer 0 with fused hh: in = xc (+ pre(x0)), out = act
        {
            size_t o1 = ((size_t)f*3 + 0)*C_;
            k_layer_mma<<<NB, 512, SMEM_MMA>>>(xc, act,
                cf_dw_w + o1*3, cf_dw_b + o1,
                cf_n1_g + o1, cf_n1_b + o1,
                cf_pw_w + o1*C_, cf_pw_b + o1,
                cf_n2_g + o1, cf_n2_b + o1,
                mask, dils[0], 0,
                cur0, cf_pre_w + (size_t)f*C_, cf_pre_b + (size_t)f*C_, 1);
        }
        // layers 1,2
        float* bin = act; float* bout = tmp;
        for (int l = 1; l < 3; l++){
            size_t o1 = ((size_t)f*3 + l)*C_;
            k_layer_mma<<<NB, 512, SMEM_MMA>>>(bin, bout,
                cf_dw_w + o1*3, cf_dw_b + o1,
                cf_n1_g + o1, cf_n1_b + o1,
                cf_pw_w + o1*C_, cf_pw_b + o1,
                cf_n2_g + o1, cf_n2_b + o1,
                mask, dils[l], (l == 2) ? 1 : 0,
                nullptr, nullptr, nullptr, 0);
            float* t_ = bin; bin = bout; bout = t_;
        }
        // result in act (L0: xc->act, L1: act->tmp, L2: tmp->act)
        k_proj29<<<BT_/32, 928>>>(act, cf_projw + (size_t)f*NPROJ*C_, cf_projb + (size_t)f*NPROJ, mask, hp);
        k_rqs<<<BT_/256, 256>>>(hp, cur1, cur0, mask);
    }
    { float* tp_ = cur0; cur0 = cur1; cur1 = tp_; }
    k_final<<<BT_/256, 256>>>(cur0, ea_m, ea_logs, mask, out);
}

// round 9
// speedup vs baseline: 3.0038x; 1.2438x over previous
#include <cuda_runtime.h>
#include <math.h>
#include <stdint.h>

#define B_   64
#define T_   1024
#define C_   192
#define BT_  (B_*T_)
#define NPROJ 29
#define NCHUNK (BT_/64)      // 1024
#define PGRID 152

#define ASTRIDE 196
#define WSTRIDE 196
#define A_ELEMS (64*ASTRIDE)
#define W_ELEMS (192*WSTRIDE)
#define RED_OFF (A_ELEMS + W_ELEMS)
#define SMEM_MMA ((RED_OFF + 1024) * 4)

// ---------------- scratch ----------------
__device__ float g_xT  [(size_t)BT_*C_];
__device__ float g_xc  [(size_t)BT_*C_];
__device__ float g_act [(size_t)BT_*C_];
__device__ float g_tmp [(size_t)BT_*C_];
__device__ float g_cond[B_*C_];
__device__ float g_z0[BT_];
__device__ float g_z1[BT_];
__device__ float g_hp[(size_t)BT_*NPROJ];

__device__ __forceinline__ float gelu_exact(float x){
    return 0.5f*x*(1.0f + erff(x*0.70710678118654752f));
}
__device__ __forceinline__ uint32_t to_tf32(float f){
    uint32_t r; asm("cvt.rna.tf32.f32 %0, %1;" : "=r"(r) : "f"(f)); return r;
}
__device__ __forceinline__ void mma1688(float* d, const uint32_t* a, const uint32_t* b){
    asm volatile("mma.sync.aligned.m16n8k8.row.col.f32.tf32.tf32.f32 "
                 "{%0,%1,%2,%3}, {%4,%5,%6,%7}, {%8,%9}, {%0,%1,%2,%3};"
                 : "+f"(d[0]), "+f"(d[1]), "+f"(d[2]), "+f"(d[3])
                 : "r"(a[0]), "r"(a[1]), "r"(a[2]), "r"(a[3]),
                   "r"(b[0]), "r"(b[1]));
}

// 16 warps: wm = w>>3 (M32 each), wn = w&7 (N24 each). acc[t(2)][n(3)][4].
__device__ __forceinline__ void mma_core(const uint32_t* Asm, const uint32_t* Wsm,
                                         float acc[2][3][4], int wm, int wn, int lane)
{
    const int r = lane >> 2, q = lane & 3;
    const uint32_t* ab = Asm + (wm*32 + r)*ASTRIDE + q;
    const uint32_t* wb = Wsm + (wn*24 + r)*WSTRIDE + q;
#pragma unroll 4
    for (int kc = 0; kc < C_; kc += 8){
        uint32_t a[2][4];
#pragma unroll
        for (int t = 0; t < 2; t++){
            const uint32_t* p = ab + t*16*ASTRIDE + kc;
            a[t][0] = p[0];
            a[t][1] = p[8*ASTRIDE];
            a[t][2] = p[4];
            a[t][3] = p[8*ASTRIDE + 4];
        }
        uint32_t b[3][2];
#pragma unroll
        for (int n = 0; n < 3; n++){
            const uint32_t* p = wb + n*8*WSTRIDE + kc;
            b[n][0] = p[0];
            b[n][1] = p[4];
        }
#pragma unroll
        for (int t = 0; t < 2; t++)
#pragma unroll
            for (int n = 0; n < 3; n++)
                mma1688(acc[t][n], a[t], b[n]);
    }
}

__device__ __forceinline__ void stage_W(const float* __restrict__ pww, uint32_t* Wsm, int tid){
#pragma unroll
    for (int j = 0; j < 18; j++){
        int i = tid + j*512;
        int n = i / 48, kq = i % 48;
        float4 v = *(const float4*)(pww + (size_t)n*C_ + kq*4);
        uint32_t* p = Wsm + n*WSTRIDE + kq*4;
        p[0] = to_tf32(v.x); p[1] = to_tf32(v.y); p[2] = to_tf32(v.z); p[3] = to_tf32(v.w);
    }
}

// ---------------- persistent fused DDS layer ----------------
// hh_mode: effective input = prew[c]*x0[bt] + preb[c] + xin[bt,c]
__global__ void __launch_bounds__(512,1) k_layer_mma(
    const float* __restrict__ xin, float* __restrict__ xout,
    const float* __restrict__ dww, const float* __restrict__ dwb,
    const float* __restrict__ n1g, const float* __restrict__ n1b,
    const float* __restrict__ pww, const float* __restrict__ pwb,
    const float* __restrict__ n2g, const float* __restrict__ n2b,
    const float* __restrict__ mask, int dil, int apply_mask,
    const float* __restrict__ x0g, const float* __restrict__ prew,
    const float* __restrict__ preb, int hh_mode)
{
    extern __shared__ uint32_t sm[];
    uint32_t* Asm = sm;
    uint32_t* Wsm = sm + A_ELEMS;
    float* red1 = (float*)(sm + RED_OFF);       // [8][64]
    float* red2 = red1 + 512;
    const int tid = threadIdx.x;
    const int w = tid >> 5, lane = tid & 31;
    const int wm = w >> 3, wn = w & 7;
    const int r = lane >> 2, q = lane & 3;

    stage_W(pww, Wsm, tid);

    // loop-invariant per-thread params (prologue lanes: c = lane + 32j)
    float c_n1g[6], c_n1b[6], c_dw0[6], c_dw1[6], c_dw2[6], c_dwb[6];
#pragma unroll
    for (int j = 0; j < 6; j++){
        int c = lane + 32*j;
        c_n1g[j] = n1g[c]; c_n1b[j] = n1b[c];
        c_dw0[j] = dww[c*3+0]; c_dw1[j] = dww[c*3+1]; c_dw2[j] = dww[c*3+2];
        c_dwb[j] = dwb[c];
    }
    // loop-invariant epilogue params (cols: wn*24 + n*8 + q*2)
    float bias0[3], bias1[3], e_g0[3], e_g1[3], e_b0[3], e_b1[3];
#pragma unroll
    for (int n = 0; n < 3; n++){
        int col = wn*24 + n*8 + q*2;
        bias0[n] = pwb[col]; bias1[n] = pwb[col+1];
        e_g0[n] = n2g[col]; e_g1[n] = n2g[col+1];
        e_b0[n] = n2b[col]; e_b1[n] = n2b[col+1];
    }

    for (int c0 = blockIdx.x; c0 < NCHUNK; c0 += gridDim.x){
        const int bt0 = c0 * 64;
        const int b = bt0 >> 10, t0 = bt0 & 1023;
        const float* mb = mask + b*T_;
        const float* xb = xin + (size_t)b*T_*C_;
        const float* x0b = hh_mode ? (x0g + b*T_) : (const float*)0;

        // ---- prologue: dwconv + LN1 + GELU -> Asm ----
#pragma unroll 1
        for (int i = 0; i < 4; i++){
            int rr = i*16 + w;               // 0..63
            int t = t0 + rr;
            int tm = t - dil, tp = t + dil;
            float mm = mb[t];
            float ml = (tm >= 0) ? mb[tm] : 0.f;
            float mr = (tp < T_) ? mb[tp] : 0.f;
            int tmc = (tm >= 0) ? tm : 0;
            int tpc = (tp < T_) ? tp : (T_-1);
            const float* xm_ = xb + (size_t)t*C_;
            const float* xl_ = xb + (size_t)tmc*C_;
            const float* xr_ = xb + (size_t)tpc*C_;
            float x0m = 0.f, x0l = 0.f, x0r = 0.f;
            if (hh_mode){ x0m = x0b[t]; x0l = x0b[tmc]; x0r = x0b[tpc]; }
            float y[6]; float s1 = 0.f, s2 = 0.f;
#pragma unroll
            for (int j = 0; j < 6; j++){
                int c = lane + 32*j;
                float vl = xl_[c], vm = xm_[c], vr = xr_[c];
                if (hh_mode){
                    float pw = prew[c], pb = preb[c];
                    vl = fmaf(pw, x0l, pb) + vl;
                    vm = fmaf(pw, x0m, pb) + vm;
                    vr = fmaf(pw, x0r, pb) + vr;
                }
                float v = fmaf(c_dw0[j], vl*ml,
                          fmaf(c_dw1[j], vm*mm,
                          fmaf(c_dw2[j], vr*mr, c_dwb[j])));
                y[j] = v; s1 += v; s2 += v*v;
            }
#pragma unroll
            for (int o = 16; o > 0; o >>= 1){
                s1 += __shfl_xor_sync(0xffffffffu, s1, o);
                s2 += __shfl_xor_sync(0xffffffffu, s2, o);
            }
            float mean = s1*(1.f/192.f);
            float var  = s2*(1.f/192.f) - mean*mean;
            float rstd = rsqrtf(var + 1e-5f);
#pragma unroll
            for (int j = 0; j < 6; j++){
                int c = lane + 32*j;
                float yn = c_n1g[j]*(y[j] - mean)*rstd + c_n1b[j];
                Asm[rr*ASTRIDE + c] = to_tf32(gelu_exact(yn));
            }
        }
        __syncthreads();                       // A ready (and red from prev chunk consumed)

        // ---- MMA + row partial sums ----
        float acc[2][3][4];
#pragma unroll
        for (int t = 0; t < 2; t++)
#pragma unroll
            for (int n = 0; n < 3; n++)
#pragma unroll
                for (int k = 0; k < 4; k++) acc[t][n][k] = 0.f;
        mma_core(Asm, Wsm, acc, wm, wn, lane);

        float s1a[2][2] = {{0,0},{0,0}}, s2a[2][2] = {{0,0},{0,0}};
#pragma unroll
        for (int t = 0; t < 2; t++)
#pragma unroll
            for (int n = 0; n < 3; n++){
                float v0 = acc[t][n][0] + bias0[n];
                float v1 = acc[t][n][1] + bias1[n];
                float v2 = acc[t][n][2] + bias0[n];
                float v3 = acc[t][n][3] + bias1[n];
                s1a[t][0] += v0 + v1; s2a[t][0] += v0*v0 + v1*v1;
                s1a[t][1] += v2 + v3; s2a[t][1] += v2*v2 + v3*v3;
            }
#pragma unroll
        for (int t = 0; t < 2; t++)
#pragma unroll
            for (int h = 0; h < 2; h++){
#pragma unroll
                for (int o = 1; o < 4; o <<= 1){
                    s1a[t][h] += __shfl_xor_sync(0xffffffffu, s1a[t][h], o);
                    s2a[t][h] += __shfl_xor_sync(0xffffffffu, s2a[t][h], o);
                }
            }
        if (q == 0){
#pragma unroll
            for (int t = 0; t < 2; t++)
#pragma unroll
                for (int h = 0; h < 2; h++){
                    int row = wm*32 + t*16 + h*8 + r;
                    red1[wn*64 + row] = s1a[t][h];
                    red2[wn*64 + row] = s2a[t][h];
                }
        }
        __syncthreads();                       // red ready; A fully consumed

        // ---- epilogue (next chunk's prologue follows barrier-free) ----
#pragma unroll
        for (int t = 0; t < 2; t++)
#pragma unroll
            for (int h = 0; h < 2; h++){
                int row = wm*32 + t*16 + h*8 + r;
                float tot1 = 0.f, tot2 = 0.f;
#pragma unroll
                for (int k = 0; k < 8; k++){ tot1 += red1[k*64+row]; tot2 += red2[k*64+row]; }
                float mean = tot1*(1.f/192.f);
                float var  = tot2*(1.f/192.f) - mean*mean;
                float rstd = rsqrtf(var + 1e-5f);
                int grow = bt0 + row;
                float m = apply_mask ? mask[grow] : 1.f;
                float x0v = hh_mode ? x0g[grow] : 0.f;
                const float* resp = xin + (size_t)grow*C_;
                float* outp = xout + (size_t)grow*C_;
#pragma unroll
                for (int n = 0; n < 3; n++){
                    int col = wn*24 + n*8 + q*2;
                    float v0 = acc[t][n][h*2+0] + bias0[n];
                    float v1 = acc[t][n][h*2+1] + bias1[n];
                    float2 res = *(const float2*)(resp + col);
                    float rx = res.x, ry = res.y;
                    if (hh_mode){
                        rx = fmaf(prew[col+0], x0v, preb[col+0]) + rx;
                        ry = fmaf(prew[col+1], x0v, preb[col+1]) + ry;
                    }
                    float2 o2;
                    o2.x = rx + gelu_exact(e_g0[n]*(v0-mean)*rstd + e_b0[n]);
                    o2.y = ry + gelu_exact(e_g1[n]*(v1-mean)*rstd + e_b1[n]);
                    if (apply_mask){ o2.x *= m; o2.y *= m; }
                    *(float2*)(outp + col) = o2;
                }
            }
    }
}

// ---------------- persistent plain tf32 MMA GEMM ----------------
__global__ void __launch_bounds__(512,1) k_gemm_mma(
    const float* __restrict__ xin, float* __restrict__ xout,
    const float* __restrict__ pww, const float* __restrict__ pwb,
    const float* __restrict__ cond, const float* __restrict__ mask)
{
    extern __shared__ uint32_t sm[];
    uint32_t* Asm = sm;
    uint32_t* Wsm = sm + A_ELEMS;
    const int tid = threadIdx.x;
    const int w = tid >> 5, lane = tid & 31;
    const int wm = w >> 3, wn = w & 7;
    const int r = lane >> 2, q = lane & 3;

    stage_W(pww, Wsm, tid);

    float pb0[3], pb1[3];
#pragma unroll
    for (int n = 0; n < 3; n++){
        int col = wn*24 + n*8 + q*2;
        pb0[n] = pwb[col]; pb1[n] = pwb[col+1];
    }

    for (int c0 = blockIdx.x; c0 < NCHUNK; c0 += gridDim.x){
        const int rb = c0 * 64;
        const int b = rb >> 10;
#pragma unroll
        for (int j = 0; j < 6; j++){
            int i = tid + j*512;
            int r2 = i / 48, kq = i % 48;
            float4 v = *(const float4*)(xin + (size_t)(rb + r2)*C_ + kq*4);
            uint32_t* p = Asm + r2*ASTRIDE + kq*4;
            p[0] = to_tf32(v.x); p[1] = to_tf32(v.y); p[2] = to_tf32(v.z); p[3] = to_tf32(v.w);
        }
        __syncthreads();

        float acc[2][3][4];
#pragma unroll
        for (int t = 0; t < 2; t++)
#pragma unroll
            for (int n = 0; n < 3; n++)
#pragma unroll
                for (int k = 0; k < 4; k++) acc[t][n][k] = 0.f;
        mma_core(Asm, Wsm, acc, wm, wn, lane);
        __syncthreads();                      // A consumed; safe for next prologue

        float bias0[3], bias1[3];
#pragma unroll
        for (int n = 0; n < 3; n++){
            bias0[n] = pb0[n]; bias1[n] = pb1[n];
            if (cond){
                int col = wn*24 + n*8 + q*2;
                bias0[n] += cond[b*C_ + col]; bias1[n] += cond[b*C_ + col+1];
            }
        }
#pragma unroll
        for (int t = 0; t < 2; t++)
#pragma unroll
            for (int h = 0; h < 2; h++){
                int row = wm*32 + t*16 + h*8 + r;
                int grow = rb + row;
                float m = mask ? mask[grow] : 1.f;
                float* outp = xout + (size_t)grow*C_;
#pragma unroll
                for (int n = 0; n < 3; n++){
                    int col = wn*24 + n*8 + q*2;
                    float2 o2;
                    o2.x = (acc[t][n][h*2+0] + bias0[n]) * m;
                    o2.y = (acc[t][n][h*2+1] + bias1[n]) * m;
                    *(float2*)(outp + col) = o2;
                }
            }
    }
}

// ---------------- transpose x: (B,C,T) -> (B,T,C) ----------------
__global__ void k_transpose(const float* __restrict__ x, float* __restrict__ xT){
    __shared__ float tile[32][33];
    int b  = blockIdx.z;
    int c0 = blockIdx.y * 32;
    int t0 = blockIdx.x * 32;
    int tx = threadIdx.x, ty = threadIdx.y;
    const float* xb = x + (size_t)b*C_*T_;
#pragma unroll
    for (int i = 0; i < 4; i++){
        int c = c0 + ty + i*8;
        tile[ty + i*8][tx] = xb[(size_t)c*T_ + t0 + tx];
    }
    __syncthreads();
    float* ob = xT + (size_t)b*T_*C_;
#pragma unroll
    for (int i = 0; i < 4; i++){
        int t = t0 + ty + i*8;
        ob[(size_t)t*C_ + c0 + tx] = tile[tx][ty + i*8];
    }
}

// ---------------- cond[b,o] ----------------
__global__ void k_cond(const float* __restrict__ embed, const float* __restrict__ cw,
                       const float* __restrict__ cb, float* __restrict__ cond){
    int b = blockIdx.x, o = threadIdx.x;
    __shared__ float se[C_];
    se[o] = embed[b*C_ + o];
    __syncthreads();
    float s = cb[o];
    const float* wr = cw + (size_t)o*C_;
#pragma unroll 8
    for (int c = 0; c < C_; c++) s = fmaf(se[c], wr[c], s);
    cond[b*C_ + o] = s;
}

// ---------------- noise -> z0/z1 ----------------
__global__ void k_noise(const float* __restrict__ noise, float* __restrict__ z0, float* __restrict__ z1){
    int idx = blockIdx.x*256 + threadIdx.x;
    int b = idx >> 10, t = idx & 1023;
    z0[idx] = noise[(size_t)b*2*T_ + t];
    z1[idx] = noise[(size_t)b*2*T_ + T_ + t];
}

// ---------------- proj 29x192 GEMM ----------------
__global__ void __launch_bounds__(928) k_proj29(
    const float* __restrict__ hh, const float* __restrict__ w,
    const float* __restrict__ bias, const float* __restrict__ mask,
    float* __restrict__ out)
{
    __shared__ float sh[32][193];
    int tid = threadIdx.x;
    size_t base = (size_t)blockIdx.x * 32 * C_;
    for (int i = tid; i < 32*C_; i += 928)
        sh[i/C_][i%C_] = hh[base + i];
    __syncthreads();
    int tl = tid & 31, p = tid >> 5;
    if (p < NPROJ){
        float s = bias[p];
        const float* wp = w + (size_t)p*C_;
#pragma unroll 8
        for (int c = 0; c < C_; c++) s = fmaf(sh[tl][c], wp[c], s);
        int bt = blockIdx.x*32 + tl;
        out[(size_t)bt*NPROJ + p] = s * mask[bt];
    }
}

// ---------------- rational-quadratic spline inverse ----------------
__global__ void k_rqs(const float* __restrict__ hp, float* __restrict__ z1,
                      float* __restrict__ z0, const float* __restrict__ mask)
{
    int bt = blockIdx.x*256 + threadIdx.x;
    const float* h = hp + (size_t)bt*NPROJ;
    const float sc = 0.07216878364870323f;

    float w[10], cw[11];
    {
        float u[10]; float mx = -1e30f;
#pragma unroll
        for (int j = 0; j < 10; j++){ u[j] = h[j]*sc; mx = fmaxf(mx, u[j]); }
        float s = 0.f;
#pragma unroll
        for (int j = 0; j < 10; j++){ u[j] = expf(u[j]-mx); s += u[j]; }
        float inv = 1.0f/s, accum = 0.f;
        cw[0] = -5.0f;
#pragma unroll
        for (int j = 0; j < 10; j++){
            float wj = 0.001f + 0.99f*u[j]*inv;
            accum += wj;
            cw[j+1] = 10.0f*accum - 5.0f;
        }
        cw[10] = 5.0f;
#pragma unroll
        for (int j = 0; j < 10; j++) w[j] = cw[j+1]-cw[j];
    }
    float hb[10], ch[11];
    {
        float u[10]; float mx = -1e30f;
#pragma unroll
        for (int j = 0; j < 10; j++){ u[j] = h[10+j]*sc; mx = fmaxf(mx, u[j]); }
        float s = 0.f;
#pragma unroll
        for (int j = 0; j < 10; j++){ u[j] = expf(u[j]-mx); s += u[j]; }
        float inv = 1.0f/s, accum = 0.f;
        ch[0] = -5.0f;
#pragma unroll
        for (int j = 0; j < 10; j++){
            float hj = 0.001f + 0.99f*u[j]*inv;
            accum += hj;
            ch[j+1] = 10.0f*accum - 5.0f;
        }
        ch[10] = 5.0f;
#pragma unroll
        for (int j = 0; j < 10; j++) hb[j] = ch[j+1]-ch[j];
    }
    float d[11];
    {
        const float ucst = 0.5413248546129181f;
        float v = log1pf(expf(ucst));
        d[0] = 0.001f + v; d[10] = d[0];
#pragma unroll
        for (int j = 1; j <= 9; j++){
            float u = h[19 + j];
            float spv = (u > 20.f) ? u : log1pf(expf(u));
            d[j] = 0.001f + spv;
        }
    }
    float xin = z1[bt];
    float xcl = fminf(fmaxf(xin, -5.f), 5.f);
    int idx = 0;
#pragma unroll
    for (int j = 0; j < 11; j++){
        float loc = ch[j] + ((j == 10) ? 1e-6f : 0.f);
        idx += (xcl >= loc) ? 1 : 0;
    }
    idx = min(max(idx - 1, 0), 9);
    float bw = w[idx], bcw = cw[idx], bh = hb[idx], bch = ch[idx];
    float d0 = d[idx], d1 = d[idx+1];
    float delta = bh / bw;
    float two = d0 + d1 - 2.f*delta;
    float y = xcl - bch;
    float a  = y*two + bh*(delta - d0);
    float bbq = bh*d0 - y*two;
    float c  = -delta*y;
    float disc = fmaxf(bbq*bbq - 4.f*a*c, 0.f);
    float root = 2.f*c / (-bbq - sqrtf(disc));
    float outv = root*bw + bcw;
    bool inside = (xin >= -5.f) && (xin <= 5.f);
    float res = inside ? outv : xin;
    float m = mask[bt];
    z1[bt] = res * m;
    z0[bt] = z0[bt] * m;
}

// ---------------- final affine ----------------
__global__ void k_final(const float* __restrict__ z, const float* __restrict__ ea_m,
                        const float* __restrict__ ea_logs, const float* __restrict__ mask,
                        float* __restrict__ out){
    int idx = blockIdx.x*256 + threadIdx.x;
    out[idx] = (z[idx] - ea_m[0]) * expf(-ea_logs[0]) * mask[idx];
}

// ================= host =================
extern "C" void kernel_launch(void* const* d_in, const int* in_sizes, int n_in,
                              void* d_out, int out_size)
{
    const float* x        = (const float*)d_in[0];
    const float* mask     = (const float*)d_in[1];
    const float* embed    = (const float*)d_in[2];
    const float* noise    = (const float*)d_in[3];
    const float* pre_w    = (const float*)d_in[4];
    const float* pre_b    = (const float*)d_in[5];
    const float* cond_w   = (const float*)d_in[6];
    const float* cond_b   = (const float*)d_in[7];
    const float* dds_dw_w = (const float*)d_in[8];
    const float* dds_dw_b = (const float*)d_in[9];
    const float* dds_pw_w = (const float*)d_in[10];
    const float* dds_pw_b = (const float*)d_in[11];
    const float* dds_n1_g = (const float*)d_in[12];
    const float* dds_n1_b = (const float*)d_in[13];
    const float* dds_n2_g = (const float*)d_in[14];
    const float* dds_n2_b = (const float*)d_in[15];
    const float* proj_w   = (const float*)d_in[16];
    const float* proj_b   = (const float*)d_in[17];
    const float* ea_m     = (const float*)d_in[18];
    const float* ea_logs  = (const float*)d_in[19];
    const float* cf_pre_w = (const float*)d_in[20];
    const float* cf_pre_b = (const float*)d_in[21];
    const float* cf_dw_w  = (const float*)d_in[22];
    const float* cf_dw_b  = (const float*)d_in[23];
    const float* cf_pw_w  = (const float*)d_in[24];
    const float* cf_pw_b  = (const float*)d_in[25];
    const float* cf_n1_g  = (const float*)d_in[26];
    const float* cf_n1_b  = (const float*)d_in[27];
    const float* cf_n2_g  = (const float*)d_in[28];
    const float* cf_n2_b  = (const float*)d_in[29];
    const float* cf_projw = (const float*)d_in[30];
    const float* cf_projb = (const float*)d_in[31];
    float* out = (float*)d_out;

    float *xT, *xc, *act, *tmp, *cond, *z0, *z1, *hp;
    cudaGetSymbolAddress((void**)&xT,   g_xT);
    cudaGetSymbolAddress((void**)&xc,   g_xc);
    cudaGetSymbolAddress((void**)&act,  g_act);
    cudaGetSymbolAddress((void**)&tmp,  g_tmp);
    cudaGetSymbolAddress((void**)&cond, g_cond);
    cudaGetSymbolAddress((void**)&z0,   g_z0);
    cudaGetSymbolAddress((void**)&z1,   g_z1);
    cudaGetSymbolAddress((void**)&hp,   g_hp);

    cudaFuncSetAttribute(k_layer_mma, cudaFuncAttributeMaxDynamicSharedMemorySize, SMEM_MMA);
    cudaFuncSetAttribute(k_gemm_mma,  cudaFuncAttributeMaxDynamicSharedMemorySize, SMEM_MMA);

    const int dils[3] = {1, 3, 9};

    {
        dim3 tb(32, 8), tg(T_/32, C_/32, B_);
        k_transpose<<<tg, tb>>>(x, xT);
    }
    k_cond<<<B_, C_>>>(embed, cond_w, cond_b, cond);
    k_gemm_mma<<<PGRID, 512, SMEM_MMA>>>(xT, act, pre_w, pre_b, cond, nullptr);
    {
        float* bin = act; float* bout = tmp;
        for (int l = 0; l < 3; l++){
            k_layer_mma<<<PGRID, 512, SMEM_MMA>>>(bin, bout,
                dds_dw_w + (size_t)l*C_*3, dds_dw_b + (size_t)l*C_,
                dds_n1_g + (size_t)l*C_, dds_n1_b + (size_t)l*C_,
                dds_pw_w + (size_t)l*C_*C_, dds_pw_b + (size_t)l*C_,
                dds_n2_g + (size_t)l*C_, dds_n2_b + (size_t)l*C_,
                mask, dils[l], (l == 2) ? 1 : 0,
                nullptr, nullptr, nullptr, 0);
            float* t_ = bin; bin = bout; bout = t_;
        }
        k_gemm_mma<<<PGRID, 512, SMEM_MMA>>>(bin, xc, proj_w, proj_b, nullptr, mask);
    }

    k_noise<<<BT_/256, 256>>>(noise, z0, z1);

    float* cur0 = z0; float* cur1 = z1;
    const int forder[3] = {3, 2, 1};
    for (int fi = 0; fi < 3; fi++){
        int f = forder[fi];
        float* tp_ = cur0; cur0 = cur1; cur1 = tp_;
        // layer 0 with fused hh: in = xc (+ pre(x0)), out = act
        {
            size_t o1 = ((size_t)f*3 + 0)*C_;
            k_layer_mma<<<PGRID, 512, SMEM_MMA>>>(xc, act,
                cf_dw_w + o1*3, cf_dw_b + o1,
                cf_n1_g + o1, cf_n1_b + o1,
                cf_pw_w + o1*C_, cf_pw_b + o1,
                cf_n2_g + o1, cf_n2_b + o1,
                mask, dils[0], 0,
                cur0, cf_pre_w + (size_t)f*C_, cf_pre_b + (size_t)f*C_, 1);
        }
        // layers 1,2
        float* bin = act; float* bout = tmp;
        for (int l = 1; l < 3; l++){
            size_t o1 = ((size_t)f*3 + l)*C_;
            k_layer_mma<<<PGRID, 512, SMEM_MMA>>>(bin, bout,
                cf_dw_w + o1*3, cf_dw_b + o1,
                cf_n1_g + o1, cf_n1_b + o1,
                cf_pw_w + o1*C_, cf_pw_b + o1,
                cf_n2_g + o1, cf_n2_b + o1,
                mask, dils[l], (l == 2) ? 1 : 0,
                nullptr, nullptr, nullptr, 0);
            float* t_ = bin; bin = bout; bout = t_;
        }
        // result in act (L0: xc->act, L1: act->tmp, L2: tmp->act)
        k_proj29<<<BT_/32, 928>>>(act, cf_projw + (size_t)f*NPROJ*C_, cf_projb + (size_t)f*NPROJ, mask, hp);
        k_rqs<<<BT_/256, 256>>>(hp, cur1, cur0, mask);
    }
    { float* tp_ = cur0; cur0 = cur1; cur1 = tp_; }
    k_final<<<BT_/256, 256>>>(cur0, ea_m, ea_logs, mask, out);
}

// round 10
// speedup vs baseline: 3.0076x; 1.0013x over previous
#include <cuda_runtime.h>
#include <math.h>
#include <stdint.h>

#define B_   64
#define T_   1024
#define C_   192
#define BT_  (B_*T_)
#define NPROJ 29
#define NCHUNK (BT_/64)      // 1024
#define PGRID 152

#define ASTRIDE 200          // == 8 mod 32 -> conflict-free LDS.64
#define WSTRIDE 200
#define A_ELEMS (64*ASTRIDE)
#define W_ELEMS (192*WSTRIDE)
#define RED_OFF (A_ELEMS + W_ELEMS)
#define SMEM_MMA ((RED_OFF + 1024) * 4)   // 208896 B

// ---------------- scratch ----------------
__device__ float g_xT  [(size_t)BT_*C_];
__device__ float g_xc  [(size_t)BT_*C_];
__device__ float g_act [(size_t)BT_*C_];
__device__ float g_tmp [(size_t)BT_*C_];
__device__ float g_cond[B_*C_];
__device__ float g_z0[BT_];
__device__ float g_z1[BT_];
__device__ float g_hp[(size_t)BT_*NPROJ];

__device__ __forceinline__ float gelu_exact(float x){
    return 0.5f*x*(1.0f + erff(x*0.70710678118654752f));
}
__device__ __forceinline__ uint32_t to_tf32(float f){
    uint32_t r; asm("cvt.rna.tf32.f32 %0, %1;" : "=r"(r) : "f"(f)); return r;
}
// within each 8-k group store order [0,4,1,5,2,6,3,7] so (q, q+4) is one LDS.64
__device__ __forceinline__ int kperm(int k){
    int o = k & 7;
    return (k & ~7) + ((o < 4) ? (o*2) : ((o-4)*2 + 1));
}
__device__ __forceinline__ void mma1688(float* d, const uint32_t* a, const uint32_t* b){
    asm volatile("mma.sync.aligned.m16n8k8.row.col.f32.tf32.tf32.f32 "
                 "{%0,%1,%2,%3}, {%4,%5,%6,%7}, {%8,%9}, {%0,%1,%2,%3};"
                 : "+f"(d[0]), "+f"(d[1]), "+f"(d[2]), "+f"(d[3])
                 : "r"(a[0]), "r"(a[1]), "r"(a[2]), "r"(a[3]),
                   "r"(b[0]), "r"(b[1]));
}

// 16 warps: wm = w>>3 (M32 each), wn = w&7 (N24 each). acc[t(2)][n(3)][4].
__device__ __forceinline__ void mma_core(const uint32_t* Asm, const uint32_t* Wsm,
                                         float acc[2][3][4], int wm, int wn, int lane)
{
    const int r = lane >> 2, q = lane & 3;
    const uint32_t* ab = Asm + (wm*32 + r)*ASTRIDE + 2*q;
    const uint32_t* wb = Wsm + (wn*24 + r)*WSTRIDE + 2*q;
#pragma unroll 4
    for (int kc = 0; kc < C_; kc += 8){
        uint2 a00 = *(const uint2*)(ab + kc);
        uint2 a08 = *(const uint2*)(ab + 8*ASTRIDE + kc);
        uint2 a10 = *(const uint2*)(ab + 16*ASTRIDE + kc);
        uint2 a18 = *(const uint2*)(ab + 24*ASTRIDE + kc);
        uint2 bv0 = *(const uint2*)(wb + kc);
        uint2 bv1 = *(const uint2*)(wb + 8*WSTRIDE + kc);
        uint2 bv2 = *(const uint2*)(wb + 16*WSTRIDE + kc);
        uint32_t a0[4] = {a00.x, a08.x, a00.y, a08.y};
        uint32_t a1[4] = {a10.x, a18.x, a10.y, a18.y};
        uint32_t b0[2] = {bv0.x, bv0.y};
        uint32_t b1[2] = {bv1.x, bv1.y};
        uint32_t b2[2] = {bv2.x, bv2.y};
        mma1688(acc[0][0], a0, b0);
        mma1688(acc[0][1], a0, b1);
        mma1688(acc[0][2], a0, b2);
        mma1688(acc[1][0], a1, b0);
        mma1688(acc[1][1], a1, b1);
        mma1688(acc[1][2], a1, b2);
    }
}

__device__ __forceinline__ void stage_W(const float* __restrict__ pww, uint32_t* Wsm, int tid){
#pragma unroll
    for (int j = 0; j < 18; j++){
        int i = tid + j*512;
        int n = i / 48, kq = i % 48;
        float4 v = *(const float4*)(pww + (size_t)n*C_ + kq*4);
        uint32_t* p = Wsm + n*WSTRIDE;
        p[kperm(kq*4+0)] = to_tf32(v.x);
        p[kperm(kq*4+1)] = to_tf32(v.y);
        p[kperm(kq*4+2)] = to_tf32(v.z);
        p[kperm(kq*4+3)] = to_tf32(v.w);
    }
}

// ---------------- persistent fused DDS layer ----------------
// hh_mode: effective input = prew[c]*x0[bt] + preb[c] + xin[bt,c]
__global__ void __launch_bounds__(512,1) k_layer_mma(
    const float* __restrict__ xin, float* __restrict__ xout,
    const float* __restrict__ dww, const float* __restrict__ dwb,
    const float* __restrict__ n1g, const float* __restrict__ n1b,
    const float* __restrict__ pww, const float* __restrict__ pwb,
    const float* __restrict__ n2g, const float* __restrict__ n2b,
    const float* __restrict__ mask, int dil, int apply_mask,
    const float* __restrict__ x0g, const float* __restrict__ prew,
    const float* __restrict__ preb, int hh_mode)
{
    extern __shared__ uint32_t sm[];
    uint32_t* Asm = sm;
    uint32_t* Wsm = sm + A_ELEMS;
    float* red1 = (float*)(sm + RED_OFF);       // [8][64]
    float* red2 = red1 + 512;
    const int tid = threadIdx.x;
    const int w = tid >> 5, lane = tid & 31;
    const int wm = w >> 3, wn = w & 7;
    const int r = lane >> 2, q = lane & 3;

    stage_W(pww, Wsm, tid);

    // interleaved column base for prologue stores: c = lane + 32j
    const int lo = lane & 7;
    const int cpos0 = (lane & ~7) + ((lo < 4) ? lo*2 : (lo-4)*2 + 1);

    // loop-invariant per-thread params (prologue lanes: c = lane + 32j)
    float c_n1g[6], c_n1b[6], c_dw0[6], c_dw1[6], c_dw2[6], c_dwb[6];
#pragma unroll
    for (int j = 0; j < 6; j++){
        int c = lane + 32*j;
        c_n1g[j] = n1g[c]; c_n1b[j] = n1b[c];
        c_dw0[j] = dww[c*3+0]; c_dw1[j] = dww[c*3+1]; c_dw2[j] = dww[c*3+2];
        c_dwb[j] = dwb[c];
    }
    // loop-invariant epilogue params (cols: wn*24 + n*8 + q*2)
    float bias0[3], bias1[3], e_g0[3], e_g1[3], e_b0[3], e_b1[3];
#pragma unroll
    for (int n = 0; n < 3; n++){
        int col = wn*24 + n*8 + q*2;
        bias0[n] = pwb[col]; bias1[n] = pwb[col+1];
        e_g0[n] = n2g[col]; e_g1[n] = n2g[col+1];
        e_b0[n] = n2b[col]; e_b1[n] = n2b[col+1];
    }

    for (int c0 = blockIdx.x; c0 < NCHUNK; c0 += gridDim.x){
        const int bt0 = c0 * 64;
        const int b = bt0 >> 10, t0 = bt0 & 1023;
        const float* mb = mask + b*T_;
        const float* xb = xin + (size_t)b*T_*C_;
        const float* x0b = hh_mode ? (x0g + b*T_) : (const float*)0;

        // ---- prologue: dwconv + LN1 + GELU -> Asm (k-interleaved) ----
#pragma unroll 1
        for (int i = 0; i < 4; i++){
            int rr = i*16 + w;               // 0..63
            int t = t0 + rr;
            int tm = t - dil, tp = t + dil;
            float mm = mb[t];
            float ml = (tm >= 0) ? mb[tm] : 0.f;
            float mr = (tp < T_) ? mb[tp] : 0.f;
            int tmc = (tm >= 0) ? tm : 0;
            int tpc = (tp < T_) ? tp : (T_-1);
            const float* xm_ = xb + (size_t)t*C_;
            const float* xl_ = xb + (size_t)tmc*C_;
            const float* xr_ = xb + (size_t)tpc*C_;
            float x0m = 0.f, x0l = 0.f, x0r = 0.f;
            if (hh_mode){ x0m = x0b[t]; x0l = x0b[tmc]; x0r = x0b[tpc]; }
            float y[6]; float s1 = 0.f, s2 = 0.f;
#pragma unroll
            for (int j = 0; j < 6; j++){
                int c = lane + 32*j;
                float vl = xl_[c], vm = xm_[c], vr = xr_[c];
                if (hh_mode){
                    float pw = prew[c], pb = preb[c];
                    vl = fmaf(pw, x0l, pb) + vl;
                    vm = fmaf(pw, x0m, pb) + vm;
                    vr = fmaf(pw, x0r, pb) + vr;
                }
                float v = fmaf(c_dw0[j], vl*ml,
                          fmaf(c_dw1[j], vm*mm,
                          fmaf(c_dw2[j], vr*mr, c_dwb[j])));
                y[j] = v; s1 += v; s2 += v*v;
            }
#pragma unroll
            for (int o = 16; o > 0; o >>= 1){
                s1 += __shfl_xor_sync(0xffffffffu, s1, o);
                s2 += __shfl_xor_sync(0xffffffffu, s2, o);
            }
            float mean = s1*(1.f/192.f);
            float var  = s2*(1.f/192.f) - mean*mean;
            float rstd = rsqrtf(var + 1e-5f);
#pragma unroll
            for (int j = 0; j < 6; j++){
                float yn = c_n1g[j]*(y[j] - mean)*rstd + c_n1b[j];
                Asm[rr*ASTRIDE + cpos0 + 32*j] = to_tf32(gelu_exact(yn));
            }
        }
        __syncthreads();                       // A ready (and red from prev chunk consumed)

        // ---- MMA + row partial sums ----
        float acc[2][3][4];
#pragma unroll
        for (int t = 0; t < 2; t++)
#pragma unroll
            for (int n = 0; n < 3; n++)
#pragma unroll
                for (int k = 0; k < 4; k++) acc[t][n][k] = 0.f;
        mma_core(Asm, Wsm, acc, wm, wn, lane);

        float s1a[2][2] = {{0,0},{0,0}}, s2a[2][2] = {{0,0},{0,0}};
#pragma unroll
        for (int t = 0; t < 2; t++)
#pragma unroll
            for (int n = 0; n < 3; n++){
                float v0 = acc[t][n][0] + bias0[n];
                float v1 = acc[t][n][1] + bias1[n];
                float v2 = acc[t][n][2] + bias0[n];
                float v3 = acc[t][n][3] + bias1[n];
                s1a[t][0] += v0 + v1; s2a[t][0] += v0*v0 + v1*v1;
                s1a[t][1] += v2 + v3; s2a[t][1] += v2*v2 + v3*v3;
            }
#pragma unroll
        for (int t = 0; t < 2; t++)
#pragma unroll
            for (int h = 0; h < 2; h++){
#pragma unroll
                for (int o = 1; o < 4; o <<= 1){
                    s1a[t][h] += __shfl_xor_sync(0xffffffffu, s1a[t][h], o);
                    s2a[t][h] += __shfl_xor_sync(0xffffffffu, s2a[t][h], o);
                }
            }
        if (q == 0){
#pragma unroll
            for (int t = 0; t < 2; t++)
#pragma unroll
                for (int h = 0; h < 2; h++){
                    int row = wm*32 + t*16 + h*8 + r;
                    red1[wn*64 + row] = s1a[t][h];
                    red2[wn*64 + row] = s2a[t][h];
                }
        }
        __syncthreads();                       // red ready; A fully consumed

        // ---- epilogue (next chunk's prologue follows barrier-free) ----
#pragma unroll
        for (int t = 0; t < 2; t++)
#pragma unroll
            for (int h = 0; h < 2; h++){
                int row = wm*32 + t*16 + h*8 + r;
                float tot1 = 0.f, tot2 = 0.f;
#pragma unroll
                for (int k = 0; k < 8; k++){ tot1 += red1[k*64+row]; tot2 += red2[k*64+row]; }
                float mean = tot1*(1.f/192.f);
                float var  = tot2*(1.f/192.f) - mean*mean;
                float rstd = rsqrtf(var + 1e-5f);
                int grow = bt0 + row;
                float m = apply_mask ? mask[grow] : 1.f;
                float x0v = hh_mode ? x0g[grow] : 0.f;
                const float* resp = xin + (size_t)grow*C_;
                float* outp = xout + (size_t)grow*C_;
#pragma unroll
                for (int n = 0; n < 3; n++){
                    int col = wn*24 + n*8 + q*2;
                    float v0 = acc[t][n][h*2+0] + bias0[n];
                    float v1 = acc[t][n][h*2+1] + bias1[n];
                    float2 res = *(const float2*)(resp + col);
                    float rx = res.x, ry = res.y;
                    if (hh_mode){
                        rx = fmaf(prew[col+0], x0v, preb[col+0]) + rx;
                        ry = fmaf(prew[col+1], x0v, preb[col+1]) + ry;
                    }
                    float2 o2;
                    o2.x = rx + gelu_exact(e_g0[n]*(v0-mean)*rstd + e_b0[n]);
                    o2.y = ry + gelu_exact(e_g1[n]*(v1-mean)*rstd + e_b1[n]);
                    if (apply_mask){ o2.x *= m; o2.y *= m; }
                    *(float2*)(outp + col) = o2;
                }
            }
    }
}

// ---------------- persistent plain tf32 MMA GEMM ----------------
__global__ void __launch_bounds__(512,1) k_gemm_mma(
    const float* __restrict__ xin, float* __restrict__ xout,
    const float* __restrict__ pww, const float* __restrict__ pwb,
    const float* __restrict__ cond, const float* __restrict__ mask)
{
    extern __shared__ uint32_t sm[];
    uint32_t* Asm = sm;
    uint32_t* Wsm = sm + A_ELEMS;
    const int tid = threadIdx.x;
    const int w = tid >> 5, lane = tid & 31;
    const int wm = w >> 3, wn = w & 7;
    const int r = lane >> 2, q = lane & 3;

    stage_W(pww, Wsm, tid);

    float pb0[3], pb1[3];
#pragma unroll
    for (int n = 0; n < 3; n++){
        int col = wn*24 + n*8 + q*2;
        pb0[n] = pwb[col]; pb1[n] = pwb[col+1];
    }

    for (int c0 = blockIdx.x; c0 < NCHUNK; c0 += gridDim.x){
        const int rb = c0 * 64;
        const int b = rb >> 10;
#pragma unroll
        for (int j = 0; j < 6; j++){
            int i = tid + j*512;
            int r2 = i / 48, kq = i % 48;
            float4 v = *(const float4*)(xin + (size_t)(rb + r2)*C_ + kq*4);
            uint32_t* p = Asm + r2*ASTRIDE;
            p[kperm(kq*4+0)] = to_tf32(v.x);
            p[kperm(kq*4+1)] = to_tf32(v.y);
            p[kperm(kq*4+2)] = to_tf32(v.z);
            p[kperm(kq*4+3)] = to_tf32(v.w);
        }
        __syncthreads();

        float acc[2][3][4];
#pragma unroll
        for (int t = 0; t < 2; t++)
#pragma unroll
            for (int n = 0; n < 3; n++)
#pragma unroll
                for (int k = 0; k < 4; k++) acc[t][n][k] = 0.f;
        mma_core(Asm, Wsm, acc, wm, wn, lane);
        __syncthreads();                      // A consumed; safe for next prologue

        float bias0[3], bias1[3];
#pragma unroll
        for (int n = 0; n < 3; n++){
            bias0[n] = pb0[n]; bias1[n] = pb1[n];
            if (cond){
                int col = wn*24 + n*8 + q*2;
                bias0[n] += cond[b*C_ + col]; bias1[n] += cond[b*C_ + col+1];
            }
        }
#pragma unroll
        for (int t = 0; t < 2; t++)
#pragma unroll
            for (int h = 0; h < 2; h++){
                int row = wm*32 + t*16 + h*8 + r;
                int grow = rb + row;
                float m = mask ? mask[grow] : 1.f;
                float* outp = xout + (size_t)grow*C_;
#pragma unroll
                for (int n = 0; n < 3; n++){
                    int col = wn*24 + n*8 + q*2;
                    float2 o2;
                    o2.x = (acc[t][n][h*2+0] + bias0[n]) * m;
                    o2.y = (acc[t][n][h*2+1] + bias1[n]) * m;
                    *(float2*)(outp + col) = o2;
                }
            }
    }
}

// ---------------- transpose x: (B,C,T) -> (B,T,C) ----------------
__global__ void k_transpose(const float* __restrict__ x, float* __restrict__ xT){
    __shared__ float tile[32][33];
    int b  = blockIdx.z;
    int c0 = blockIdx.y * 32;
    int t0 = blockIdx.x * 32;
    int tx = threadIdx.x, ty = threadIdx.y;
    const float* xb = x + (size_t)b*C_*T_;
#pragma unroll
    for (int i = 0; i < 4; i++){
        int c = c0 + ty + i*8;
        tile[ty + i*8][tx] = xb[(size_t)c*T_ + t0 + tx];
    }
    __syncthreads();
    float* ob = xT + (size_t)b*T_*C_;
#pragma unroll
    for (int i = 0; i < 4; i++){
        int t = t0 + ty + i*8;
        ob[(size_t)t*C_ + c0 + tx] = tile[tx][ty + i*8];
    }
}

// ---------------- cond[b,o] ----------------
__global__ void k_cond(const float* __restrict__ embed, const float* __restrict__ cw,
                       const float* __restrict__ cb, float* __restrict__ cond){
    int b = blockIdx.x, o = threadIdx.x;
    __shared__ float se[C_];
    se[o] = embed[b*C_ + o];
    __syncthreads();
    float s = cb[o];
    const float* wr = cw + (size_t)o*C_;
#pragma unroll 8
    for (int c = 0; c < C_; c++) s = fmaf(se[c], wr[c], s);
    cond[b*C_ + o] = s;
}

// ---------------- noise -> z0/z1 ----------------
__global__ void k_noise(const float* __restrict__ noise, float* __restrict__ z0, float* __restrict__ z1){
    int idx = blockIdx.x*256 + threadIdx.x;
    int b = idx >> 10, t = idx & 1023;
    z0[idx] = noise[(size_t)b*2*T_ + t];
    z1[idx] = noise[(size_t)b*2*T_ + T_ + t];
}

// ---------------- proj 29x192 GEMM ----------------
__global__ void __launch_bounds__(928) k_proj29(
    const float* __restrict__ hh, const float* __restrict__ w,
    const float* __restrict__ bias, const float* __restrict__ mask,
    float* __restrict__ out)
{
    __shared__ float sh[32][193];
    int tid = threadIdx.x;
    size_t base = (size_t)blockIdx.x * 32 * C_;
    for (int i = tid; i < 32*C_; i += 928)
        sh[i/C_][i%C_] = hh[base + i];
    __syncthreads();
    int tl = tid & 31, p = tid >> 5;
    if (p < NPROJ){
        float s = bias[p];
        const float* wp = w + (size_t)p*C_;
#pragma unroll 8
        for (int c = 0; c < C_; c++) s = fmaf(sh[tl][c], wp[c], s);
        int bt = blockIdx.x*32 + tl;
        out[(size_t)bt*NPROJ + p] = s * mask[bt];
    }
}

// ---------------- rational-quadratic spline inverse ----------------
__global__ void k_rqs(const float* __restrict__ hp, float* __restrict__ z1,
                      float* __restrict__ z0, const float* __restrict__ mask)
{
    int bt = blockIdx.x*256 + threadIdx.x;
    const float* h = hp + (size_t)bt*NPROJ;
    const float sc = 0.07216878364870323f;

    float w[10], cw[11];
    {
        float u[10]; float mx = -1e30f;
#pragma unroll
        for (int j = 0; j < 10; j++){ u[j] = h[j]*sc; mx = fmaxf(mx, u[j]); }
        float s = 0.f;
#pragma unroll
        for (int j = 0; j < 10; j++){ u[j] = expf(u[j]-mx); s += u[j]; }
        float inv = 1.0f/s, accum = 0.f;
        cw[0] = -5.0f;
#pragma unroll
        for (int j = 0; j < 10; j++){
            float wj = 0.001f + 0.99f*u[j]*inv;
            accum += wj;
            cw[j+1] = 10.0f*accum - 5.0f;
        }
        cw[10] = 5.0f;
#pragma unroll
        for (int j = 0; j < 10; j++) w[j] = cw[j+1]-cw[j];
    }
    float hb[10], ch[11];
    {
        float u[10]; float mx = -1e30f;
#pragma unroll
        for (int j = 0; j < 10; j++){ u[j] = h[10+j]*sc; mx = fmaxf(mx, u[j]); }
        float s = 0.f;
#pragma unroll
        for (int j = 0; j < 10; j++){ u[j] = expf(u[j]-mx); s += u[j]; }
        float inv = 1.0f/s, accum = 0.f;
        ch[0] = -5.0f;
#pragma unroll
        for (int j = 0; j < 10; j++){
            float hj = 0.001f + 0.99f*u[j]*inv;
            accum += hj;
            ch[j+1] = 10.0f*accum - 5.0f;
        }
        ch[10] = 5.0f;
#pragma unroll
        for (int j = 0; j < 10; j++) hb[j] = ch[j+1]-ch[j];
    }
    float d[11];
    {
        const float ucst = 0.5413248546129181f;
        float v = log1pf(expf(ucst));
        d[0] = 0.001f + v; d[10] = d[0];
#pragma unroll
        for (int j = 1; j <= 9; j++){
            float u = h[19 + j];
            float spv = (u > 20.f) ? u : log1pf(expf(u));
            d[j] = 0.001f + spv;
        }
    }
    float xin = z1[bt];
    float xcl = fminf(fmaxf(xin, -5.f), 5.f);
    int idx = 0;
#pragma unroll
    for (int j = 0; j < 11; j++){
        float loc = ch[j] + ((j == 10) ? 1e-6f : 0.f);
        idx += (xcl >= loc) ? 1 : 0;
    }
    idx = min(max(idx - 1, 0), 9);
    float bw = w[idx], bcw = cw[idx], bh = hb[idx], bch = ch[idx];
    float d0 = d[idx], d1 = d[idx+1];
    float delta = bh / bw;
    float two = d0 + d1 - 2.f*delta;
    float y = xcl - bch;
    float a  = y*two + bh*(delta - d0);
    float bbq = bh*d0 - y*two;
    float c  = -delta*y;
    float disc = fmaxf(bbq*bbq - 4.f*a*c, 0.f);
    float root = 2.f*c / (-bbq - sqrtf(disc));
    float outv = root*bw + bcw;
    bool inside = (xin >= -5.f) && (xin <= 5.f);
    float res = inside ? outv : xin;
    float m = mask[bt];
    z1[bt] = res * m;
    z0[bt] = z0[bt] * m;
}

// ---------------- final affine ----------------
__global__ void k_final(const float* __restrict__ z, const float* __restrict__ ea_m,
                        const float* __restrict__ ea_logs, const float* __restrict__ mask,
                        float* __restrict__ out){
    int idx = blockIdx.x*256 + threadIdx.x;
    out[idx] = (z[idx] - ea_m[0]) * expf(-ea_logs[0]) * mask[idx];
}

// ================= host =================
extern "C" void kernel_launch(void* const* d_in, const int* in_sizes, int n_in,
                              void* d_out, int out_size)
{
    const float* x        = (const float*)d_in[0];
    const float* mask     = (const float*)d_in[1];
    const float* embed    = (const float*)d_in[2];
    const float* noise    = (const float*)d_in[3];
    const float* pre_w    = (const float*)d_in[4];
    const float* pre_b    = (const float*)d_in[5];
    const float* cond_w   = (const float*)d_in[6];
    const float* cond_b   = (const float*)d_in[7];
    const float* dds_dw_w = (const float*)d_in[8];
    const float* dds_dw_b = (const float*)d_in[9];
    const float* dds_pw_w = (const float*)d_in[10];
    const float* dds_pw_b = (const float*)d_in[11];
    const float* dds_n1_g = (const float*)d_in[12];
    const float* dds_n1_b = (const float*)d_in[13];
    const float* dds_n2_g = (const float*)d_in[14];
    const float* dds_n2_b = (const float*)d_in[15];
    const float* proj_w   = (const float*)d_in[16];
    const float* proj_b   = (const float*)d_in[17];
    const float* ea_m     = (const float*)d_in[18];
    const float* ea_logs  = (const float*)d_in[19];
    const float* cf_pre_w = (const float*)d_in[20];
    const float* cf_pre_b = (const float*)d_in[21];
    const float* cf_dw_w  = (const float*)d_in[22];
    const float* cf_dw_b  = (const float*)d_in[23];
    const float* cf_pw_w  = (const float*)d_in[24];
    const float* cf_pw_b  = (const float*)d_in[25];
    const float* cf_n1_g  = (const float*)d_in[26];
    const float* cf_n1_b  = (const float*)d_in[27];
    const float* cf_n2_g  = (const float*)d_in[28];
    const float* cf_n2_b  = (const float*)d_in[29];
    const float* cf_projw = (const float*)d_in[30];
    const float* cf_projb = (const float*)d_in[31];
    float* out = (float*)d_out;

    float *xT, *xc, *act, *tmp, *cond, *z0, *z1, *hp;
    cudaGetSymbolAddress((void**)&xT,   g_xT);
    cudaGetSymbolAddress((void**)&xc,   g_xc);
    cudaGetSymbolAddress((void**)&act,  g_act);
    cudaGetSymbolAddress((void**)&tmp,  g_tmp);
    cudaGetSymbolAddress((void**)&cond, g_cond);
    cudaGetSymbolAddress((void**)&z0,   g_z0);
    cudaGetSymbolAddress((void**)&z1,   g_z1);
    cudaGetSymbolAddress((void**)&hp,   g_hp);

    cudaFuncSetAttribute(k_layer_mma, cudaFuncAttributeMaxDynamicSharedMemorySize, SMEM_MMA);
    cudaFuncSetAttribute(k_gemm_mma,  cudaFuncAttributeMaxDynamicSharedMemorySize, SMEM_MMA);

    const int dils[3] = {1, 3, 9};

    {
        dim3 tb(32, 8), tg(T_/32, C_/32, B_);
        k_transpose<<<tg, tb>>>(x, xT);
    }
    k_cond<<<B_, C_>>>(embed, cond_w, cond_b, cond);
    k_gemm_mma<<<PGRID, 512, SMEM_MMA>>>(xT, act, pre_w, pre_b, cond, nullptr);
    {
        float* bin = act; float* bout = tmp;
        for (int l = 0; l < 3; l++){
            k_layer_mma<<<PGRID, 512, SMEM_MMA>>>(bin, bout,
                dds_dw_w + (size_t)l*C_*3, dds_dw_b + (size_t)l*C_,
                dds_n1_g + (size_t)l*C_, dds_n1_b + (size_t)l*C_,
                dds_pw_w + (size_t)l*C_*C_, dds_pw_b + (size_t)l*C_,
                dds_n2_g + (size_t)l*C_, dds_n2_b + (size_t)l*C_,
                mask, dils[l], (l == 2) ? 1 : 0,
                nullptr, nullptr, nullptr, 0);
            float* t_ = bin; bin = bout; bout = t_;
        }
        k_gemm_mma<<<PGRID, 512, SMEM_MMA>>>(bin, xc, proj_w, proj_b, nullptr, mask);
    }

    k_noise<<<BT_/256, 256>>>(noise, z0, z1);

    float* cur0 = z0; float* cur1 = z1;
    const int forder[3] = {3, 2, 1};
    for (int fi = 0; fi < 3; fi++){
        int f = forder[fi];
        float* tp_ = cur0; cur0 = cur1; cur1 = tp_;
        // layer 0 with fused hh: in = xc (+ pre(x0)), out = act
        {
            size_t o1 = ((size_t)f*3 + 0)*C_;
            k_layer_mma<<<PGRID, 512, SMEM_MMA>>>(xc, act,
                cf_dw_w + o1*3, cf_dw_b + o1,
                cf_n1_g + o1, cf_n1_b + o1,
                cf_pw_w + o1*C_, cf_pw_b + o1,
                cf_n2_g + o1, cf_n2_b + o1,
                mask, dils[0], 0,
                cur0, cf_pre_w + (size_t)f*C_, cf_pre_b + (size_t)f*C_, 1);
        }
        // layers 1,2
        float* bin = act; float* bout = tmp;
        for (int l = 1; l < 3; l++){
            size_t o1 = ((size_t)f*3 + l)*C_;
            k_layer_mma<<<PGRID, 512, SMEM_MMA>>>(bin, bout,
                cf_dw_w + o1*3, cf_dw_b + o1,
                cf_n1_g + o1, cf_n1_b + o1,
                cf_pw_w + o1*C_, cf_pw_b + o1,
                cf_n2_g + o1, cf_n2_b + o1,
                mask, dils[l], (l == 2) ? 1 : 0,
                nullptr, nullptr, nullptr, 0);
            float* t_ = bin; bin = bout; bout = t_;
        }
        // result in act (L0: xc->act, L1: act->tmp, L2: tmp->act)
        k_proj29<<<BT_/32, 928>>>(act, cf_projw + (size_t)f*NPROJ*C_, cf_projb + (size_t)f*NPROJ, mask, hp);
        k_rqs<<<BT_/256, 256>>>(hp, cur1, cur0, mask);
    }
    { float* tp_ = cur0; cur0 = cur1; cur1 = tp_; }
    k_final<<<BT_/256, 256>>>(cur0, ea_m, ea_logs, mask, out);
}